// round 13
// baseline (speedup 1.0000x reference)
#include <cuda_runtime.h>
#include <cuda_fp16.h>
#include <cstdint>

// Problem constants
#define NB   4
#define NS   2048
#define NDM  1024
#define NH   16
#define NM   (NB * NS)      // 8192 rows

// ---------------------------------------------------------------------------
// Device scratch
// ---------------------------------------------------------------------------
__device__ __half g_Qh[NB * NH * NS * 64];   // fp16 heads [B,H,S,64] (Q pre-scaled)
__device__ __half g_Kh[NB * NH * NS * 64];
__device__ __half g_Vh[NB * NH * NS * 64];
__device__ __half g_ctxh[NM * NDM];          // fp16 ctx [B*S, H*Dv]

__device__ __half g_WTq[NDM * NDM];          // fp16 W^T [n][k]
__device__ __half g_WTk[NDM * NDM];
__device__ __half g_WTv[NDM * NDM];
__device__ __half g_WTo[NDM * NDM];

// scale folded into Q heads: 1/sqrt(64) * log2(e)
#define QSCALE 0.18033688011112042f
#define ONES_H2 0x3C003C00u      // half2(1.0, 1.0)

// ---------------------------------------------------------------------------
// mma / ldmatrix / cp.async helpers
// ---------------------------------------------------------------------------
__device__ __forceinline__ uint32_t smem_u32(const void* p) {
    uint32_t a;
    asm("{ .reg .u64 t; cvta.to.shared.u64 t, %1; cvt.u32.u64 %0, t; }"
        : "=r"(a) : "l"(p));
    return a;
}

__device__ __forceinline__ void ldsm4(uint32_t r[4], uint32_t addr) {
    asm volatile("ldmatrix.sync.aligned.m8n8.x4.shared.b16 {%0,%1,%2,%3}, [%4];"
                 : "=r"(r[0]), "=r"(r[1]), "=r"(r[2]), "=r"(r[3]) : "r"(addr));
}

__device__ __forceinline__ void ldsm4t(uint32_t r[4], uint32_t addr) {
    asm volatile("ldmatrix.sync.aligned.m8n8.x4.trans.shared.b16 {%0,%1,%2,%3}, [%4];"
                 : "=r"(r[0]), "=r"(r[1]), "=r"(r[2]), "=r"(r[3]) : "r"(addr));
}

__device__ __forceinline__ void mma_f16(float c[4], const uint32_t a[4],
                                        uint32_t b0, uint32_t b1) {
    asm volatile(
        "mma.sync.aligned.m16n8k16.row.col.f32.f16.f16.f32 "
        "{%0,%1,%2,%3}, {%4,%5,%6,%7}, {%8,%9}, {%0,%1,%2,%3};"
        : "+f"(c[0]), "+f"(c[1]), "+f"(c[2]), "+f"(c[3])
        : "r"(a[0]), "r"(a[1]), "r"(a[2]), "r"(a[3]), "r"(b0), "r"(b1));
}

__device__ __forceinline__ void cp16(uint32_t dst, const void* src) {
    asm volatile("cp.async.cg.shared.global [%0], [%1], 16;" :: "r"(dst), "l"(src));
}
#define CP_COMMIT() asm volatile("cp.async.commit_group;")
#define CP_WAIT0()  asm volatile("cp.async.wait_group 0;")
#define CP_WAIT1()  asm volatile("cp.async.wait_group 1;")
#define CP_WAIT2()  asm volatile("cp.async.wait_group 2;")

__device__ __forceinline__ float ex2(float x) {
    float r;
    asm("ex2.approx.f32 %0, %1;" : "=f"(r) : "f"(x));
    return r;
}

__device__ __forceinline__ uint32_t ex2h2(float a, float b) {
    __half2 h = __float22half2_rn(make_float2(a, b));
    uint32_t u = *(uint32_t*)&h;
    asm("ex2.approx.f16x2 %0, %0;" : "+r"(u));
    return u;
}

// ---------------------------------------------------------------------------
// Weight transpose: W [k][n] fp32 -> WT [n][k] fp16, batched over z
// ---------------------------------------------------------------------------
__global__ __launch_bounds__(256) void wtrans4_kernel(const float* __restrict__ w0,
                                                      const float* __restrict__ w1,
                                                      const float* __restrict__ w2,
                                                      const float* __restrict__ w3,
                                                      __half* t0, __half* t1,
                                                      __half* t2, __half* t3) {
    __shared__ float t[32][33];
    const int z = blockIdx.z;
    const float* W = (z == 0) ? w0 : (z == 1) ? w1 : (z == 2) ? w2 : w3;
    __half* WT = (z == 0) ? t0 : (z == 1) ? t1 : (z == 2) ? t2 : t3;
    const int tx = threadIdx.x & 31;
    const int ty = threadIdx.x >> 5;
    const int bn = blockIdx.x * 32;
    const int bk = blockIdx.y * 32;
#pragma unroll
    for (int i = 0; i < 4; i++)
        t[ty + 8 * i][tx] = W[(size_t)(bk + ty + 8 * i) * NDM + bn + tx];
    __syncthreads();
#pragma unroll
    for (int i = 0; i < 4; i++)
        WT[(size_t)(bn + ty + 8 * i) * NDM + bk + tx] =
            __float2half(t[tx][ty + 8 * i]);
}

// ---------------------------------------------------------------------------
// Shared GEMM constants
// ---------------------------------------------------------------------------
#define GW 20                        // 32-bit words per smem row (BK=32 tiles)
#define GSTG 10240                   // bytes per BK=32 stage (128 rows)
#define QKV_SMEM (2 * GSTG + 4 * GSTG)   // 61440

// BK=64 tiles for gemm_out
#define GW2 36                       // words per row (64 halves + 8 pad)
#define OSTG 18432                   // bytes per BK=64 stage (128 rows)
#define OUT_SMEM (3 * 2 * OSTG)      // 3 stages x (A+B) = 110592

// ---------------------------------------------------------------------------
// QKV projection (R9-proven shape): 256 threads, warp tile 32x64.
// A fp32 direct (LDG+cvt+STS, 2-stage), B fp16 cp.async 4-stage.
// Epilogue: fp16 heads [B,H,S,64], scaled.
// ---------------------------------------------------------------------------
__global__ __launch_bounds__(256, 2) void gemm_qkv(const float* __restrict__ Qf,
                                                   const float* __restrict__ Kf,
                                                   const float* __restrict__ Vf,
                                                   const __half* __restrict__ wtq,
                                                   const __half* __restrict__ wtk,
                                                   const __half* __restrict__ wtv,
                                                   __half* qh, __half* kh, __half* vh) {
    extern __shared__ __align__(16) uint8_t gsm[];
    const uint32_t base = smem_u32(gsm);

    const int z = blockIdx.z;
    const float* A   = (z == 0) ? Qf : (z == 1) ? Kf : Vf;
    const __half* BT = (z == 0) ? wtq : (z == 1) ? wtk : wtv;
    __half* C        = (z == 0) ? qh : (z == 1) ? kh : vh;
    const float scale = (z == 0) ? QSCALE : 1.0f;

    const int tid  = threadIdx.x;
    const int lane = tid & 31;
    const int wid  = tid >> 5;
    const int lr   = lane >> 2;
    const int lq   = lane & 3;
    const int wm0  = (wid & 3) * 32;
    const int wn0  = (wid >> 2) * 64;
    const int m0   = blockIdx.y * 128;
    const int n0   = blockIdx.x * 128;

    const int a_row = wm0 + (lane & 7) + (lane & 8);
    const int a_wrd = (lane >> 4) << 2;
    const int b_row = wn0 + (lane & 7) + ((lane & 16) >> 1);
    const int b_wrd = (lane & 8) ? 4 : 0;

    const int br = tid >> 2;          // 0..63
    const int bc = tid & 3;
    const uint8_t* Bg = (const uint8_t*)BT + (size_t)n0 * 2048 + bc * 16;

    auto cpB = [&](int c) {
        const uint32_t bB = base + 2 * GSTG + (uint32_t)(c & 3) * GSTG;
        const size_t koff = (size_t)c * 64;
#pragma unroll
        for (int i = 0; i < 2; i++) {
            const uint32_t so = (uint32_t)((br + 64 * i) * GW + bc * 4) * 4;
            cp16(bB + so, Bg + (size_t)(br + 64 * i) * 2048 + koff);
        }
        CP_COMMIT();
    };

    auto ldgA = [&](int c, float4 ra[4]) {
#pragma unroll
        for (int i = 0; i < 4; i++) {
            const int gidx = tid + 256 * i;
            const int r = gidx >> 3, seg = gidx & 7;
            ra[i] = *(const float4*)(A + (size_t)(m0 + r) * NDM + c * 32 + seg * 4);
        }
    };
    auto stsA = [&](int c, const float4 ra[4]) {
        const uint32_t aB = base + (uint32_t)(c & 1) * GSTG;
#pragma unroll
        for (int i = 0; i < 4; i++) {
            const int gidx = tid + 256 * i;
            const int r = gidx >> 3, seg = gidx & 7;
            __half2 h0 = __float22half2_rn(make_float2(ra[i].x, ra[i].y));
            __half2 h1 = __float22half2_rn(make_float2(ra[i].z, ra[i].w));
            uint2 u = make_uint2(*(uint32_t*)&h0, *(uint32_t*)&h1);
            *(uint2*)(gsm + (aB - base) + (uint32_t)(r * GW + seg * 2) * 4) = u;
        }
    };

    float acc[2][8][4];
#pragma unroll
    for (int mi = 0; mi < 2; mi++)
#pragma unroll
        for (int nt = 0; nt < 8; nt++)
#pragma unroll
            for (int v = 0; v < 4; v++) acc[mi][nt][v] = 0.f;

    float4 ra[4];
    ldgA(0, ra);
    cpB(0); cpB(1); cpB(2);
    stsA(0, ra);
    ldgA(1, ra);

    for (int c = 0; c < 32; c++) {
        if (c < 29) CP_WAIT2(); else CP_WAIT0();
        __syncthreads();
        if (c + 3 < 32) cpB(c + 3);
        if (c + 1 < 32) stsA(c + 1, ra);
        if (c + 2 < 32) ldgA(c + 2, ra);

        const uint32_t aB = base + (uint32_t)(c & 1) * GSTG;
        const uint32_t bB = base + 2 * GSTG + (uint32_t)(c & 3) * GSTG;

#pragma unroll
        for (int s = 0; s < 2; s++) {
            uint32_t a[2][4];
            ldsm4(a[0], aB + (uint32_t)((a_row)*GW + s * 8 + a_wrd) * 4);
            ldsm4(a[1], aB + (uint32_t)((a_row + 16) * GW + s * 8 + a_wrd) * 4);
#pragma unroll
            for (int np = 0; np < 4; np++) {
                uint32_t bb[4];
                ldsm4(bb, bB + (uint32_t)((b_row + np * 16) * GW + s * 8 + b_wrd) * 4);
                mma_f16(acc[0][2 * np],     a[0], bb[0], bb[1]);
                mma_f16(acc[1][2 * np],     a[1], bb[0], bb[1]);
                mma_f16(acc[0][2 * np + 1], a[0], bb[2], bb[3]);
                mma_f16(acc[1][2 * np + 1], a[1], bb[2], bb[3]);
            }
        }
    }

#pragma unroll
    for (int mi = 0; mi < 2; mi++) {
        const int row0 = m0 + wm0 + mi * 16 + lr;
#pragma unroll
        for (int nt = 0; nt < 8; nt++) {
            const int col = wn0 + nt * 8 + 2 * lq;
            __half2 v0 = __float22half2_rn(
                make_float2(acc[mi][nt][0] * scale, acc[mi][nt][1] * scale));
            __half2 v1 = __float22half2_rn(
                make_float2(acc[mi][nt][2] * scale, acc[mi][nt][3] * scale));
            const int gcol = n0 + col;
            const int h = gcol >> 6, d = gcol & 63;
            const int b0i = row0 >> 11, s0 = row0 & 2047;
            *(uint32_t*)&C[(size_t)((b0i * NH + h) * NS + s0) * 64 + d] = *(uint32_t*)&v0;
            const int row1 = row0 + 8;
            const int b1i = row1 >> 11, s1 = row1 & 2047;
            *(uint32_t*)&C[(size_t)((b1i * NH + h) * NS + s1) * 64 + d] = *(uint32_t*)&v1;
        }
    }
}

// ---------------------------------------------------------------------------
// Output projection: 128 threads, warp tile 64x64, BK=64, 3-stage cp.async.
// One barrier per chunk; 16 chunks. Epilogue: fp32 out + residual.
// ---------------------------------------------------------------------------
__global__ __launch_bounds__(128, 2) void gemm_out(const __half* __restrict__ A,
                                                   const __half* __restrict__ BT,
                                                   float* __restrict__ C,
                                                   const float* __restrict__ resid) {
    extern __shared__ __align__(16) uint8_t gsm[];
    const uint32_t base = smem_u32(gsm);

    const int tid  = threadIdx.x;
    const int lane = tid & 31;
    const int wid  = tid >> 5;
    const int lr   = lane >> 2;
    const int lq   = lane & 3;
    const int wm0  = (wid & 1) * 64;
    const int wn0  = (wid >> 1) * 64;
    const int m0   = blockIdx.y * 128;
    const int n0   = blockIdx.x * 128;

    const int a_row = wm0 + (lane & 7) + (lane & 8);
    const int a_wrd = (lane >> 4) << 2;
    const int b_row = wn0 + (lane & 7) + ((lane & 16) >> 1);
    const int b_wrd = (lane & 8) ? 4 : 0;

    const uint8_t* Ag = (const uint8_t*)A + (size_t)m0 * 2048;
    const uint8_t* Bg = (const uint8_t*)BT + (size_t)n0 * 2048;

    // chunk = 128 rows x 128 B (64 halves) per operand = 1024 x 16B; 8/thread each
    auto prefetch = [&](int c) {
        const int stg = c % 3;
        const uint32_t aB = base + (uint32_t)stg * OSTG;
        const uint32_t bB = base + 3 * OSTG + (uint32_t)stg * OSTG;
        const size_t koff = (size_t)c * 128;
#pragma unroll
        for (int i = 0; i < 8; i++) {
            const int idx = tid + 128 * i;
            const int r = idx >> 3, seg = idx & 7;
            const uint32_t so = (uint32_t)(r * GW2 + seg * 4) * 4;
            cp16(aB + so, Ag + (size_t)r * 2048 + koff + seg * 16);
            cp16(bB + so, Bg + (size_t)r * 2048 + koff + seg * 16);
        }
        CP_COMMIT();
    };

    float acc[4][8][4];
#pragma unroll
    for (int mi = 0; mi < 4; mi++)
#pragma unroll
        for (int nt = 0; nt < 8; nt++)
#pragma unroll
            for (int v = 0; v < 4; v++) acc[mi][nt][v] = 0.f;

    prefetch(0);
    prefetch(1);

    for (int c = 0; c < 16; c++) {
        if (c < 15) CP_WAIT1(); else CP_WAIT0();
        __syncthreads();                 // all warps done with stage (c-1)%3
        if (c + 2 < 16) prefetch(c + 2); // overwrites stage (c-1)%3 — safe

        const int stg = c % 3;
        const uint32_t aB = base + (uint32_t)stg * OSTG;
        const uint32_t bB = base + 3 * OSTG + (uint32_t)stg * OSTG;

#pragma unroll
        for (int s = 0; s < 4; s++) {
            uint32_t a[4][4];
#pragma unroll
            for (int mi = 0; mi < 4; mi++)
                ldsm4(a[mi], aB + (uint32_t)((a_row + mi * 16) * GW2 + s * 8 + a_wrd) * 4);
#pragma unroll
            for (int np = 0; np < 4; np++) {
                uint32_t bb[4];
                ldsm4(bb, bB + (uint32_t)((b_row + np * 16) * GW2 + s * 8 + b_wrd) * 4);
#pragma unroll
                for (int mi = 0; mi < 4; mi++) {
                    mma_f16(acc[mi][2 * np],     a[mi], bb[0], bb[1]);
                    mma_f16(acc[mi][2 * np + 1], a[mi], bb[2], bb[3]);
                }
            }
        }
    }

#pragma unroll
    for (int mi = 0; mi < 4; mi++) {
        const int row0 = m0 + wm0 + mi * 16 + lr;
#pragma unroll
        for (int nt = 0; nt < 8; nt++) {
            const int col = n0 + wn0 + nt * 8 + 2 * lq;
            float2 q0 = *(const float2*)&resid[(size_t)row0 * NDM + col];
            float2 q1 = *(const float2*)&resid[(size_t)(row0 + 8) * NDM + col];
            *(float2*)&C[(size_t)row0 * NDM + col] =
                make_float2(acc[mi][nt][0] + q0.x, acc[mi][nt][1] + q0.y);
            *(float2*)&C[(size_t)(row0 + 8) * NDM + col] =
                make_float2(acc[mi][nt][2] + q1.x, acc[mi][nt][3] + q1.y);
        }
    }
}

// ---------------------------------------------------------------------------
// Flash attention, causal, fp16 mma m16n8k16. 3-stage K/V cp.async ring
// (wait is for data requested two iterations earlier).
// ---------------------------------------------------------------------------
#define ST 72
#define ATTN_SMEM_BYTES ((128 + 3 * 64 + 3 * 64) * ST * 2)   // 73728

__global__ __launch_bounds__(256, 2) void attn_h(const __half* __restrict__ Qh,
                                                 const __half* __restrict__ Kh,
                                                 const __half* __restrict__ Vh,
                                                 __half* __restrict__ ctx) {
    extern __shared__ __half smh[];
    __half* Qs = smh;
    __half* Ks0 = Qs + 128 * ST;              // [3][64][ST]
    __half* Vs0 = Ks0 + 3 * 64 * ST;          // [3][64][ST]
    const uint32_t qsU = smem_u32(Qs);
    const uint32_t ksU = smem_u32(Ks0);
    const uint32_t vsU = smem_u32(Vs0);
    const uint32_t KVSTG = 64 * ST * 2;

    const int tid  = threadIdx.x;
    const int lane = tid & 31;
    const int wid  = tid >> 5;
    const int lr   = lane >> 2;
    const int lq   = lane & 3;

    const int qt = gridDim.x - 1 - blockIdx.x;
    const int bh = blockIdx.y;

    const __half* Qb = Qh + (size_t)bh * NS * 64;
    const __half* Kb = Kh + (size_t)bh * NS * 64;
    const __half* Vb = Vh + (size_t)bh * NS * 64;

    auto prefetch = [&](int kt) {
        const int st = kt % 3;
#pragma unroll
        for (int i = 0; i < 2; i++) {
            const int idx = tid + 256 * i;
            const int r = idx >> 3, cu = idx & 7;
            cp16(ksU + (uint32_t)st * KVSTG + (uint32_t)(r * ST + cu * 8) * 2,
                 Kb + (size_t)(kt * 64 + r) * 64 + cu * 8);
            cp16(vsU + (uint32_t)st * KVSTG + (uint32_t)(r * ST + cu * 8) * 2,
                 Vb + (size_t)(kt * 64 + r) * 64 + cu * 8);
        }
        CP_COMMIT();
    };

    const int ktmax = 2 * qt + 1;

    prefetch(0);
    prefetch(1);   // ktmax >= 1 always
#pragma unroll
    for (int i = 0; i < 4; i++) {
        const int idx = tid + 256 * i;
        const int r = idx >> 3, cu = idx & 7;
        *(uint4*)&Qs[r * ST + cu * 8] =
            *(const uint4*)(Qb + (size_t)(qt * 128 + r) * 64 + cu * 8);
    }
    __syncthreads();

    uint32_t qf[4][4];
    {
        const int arow = wid * 16 + (lane & 7) + (lane & 8);
        const int acol = (lane & 16) >> 1;
#pragma unroll
        for (int s = 0; s < 4; s++)
            ldsm4(qf[s], qsU + (uint32_t)(arow * ST + s * 16 + acol) * 2);
    }

    float o[8][4];
#pragma unroll
    for (int nt = 0; nt < 8; nt++)
#pragma unroll
        for (int v = 0; v < 4; v++) o[nt][v] = 0.f;
    float osum[4] = {0.f, 0.f, 0.f, 0.f};
    float mrow0 = -1e30f, mrow1 = -1e30f;

    const int qrow0 = qt * 128 + wid * 16 + lr;
    const int qrow1 = qrow0 + 8;

    const int kb_row = (lane & 7) + ((lane & 16) >> 1);
    const int kb_col = (lane & 8) ? 8 : 0;
    const int vb_row = (lane & 7) + (lane & 8);
    const int vb_col = (lane & 16) >> 1;

    for (int kt = 0; kt <= ktmax; kt++) {
        if (kt < ktmax) CP_WAIT1(); else CP_WAIT0();
        __syncthreads();                       // stage (kt-1)%3 reads retired
        if (kt + 2 <= ktmax) prefetch(kt + 2); // overwrites stage (kt-1)%3

        const int st = kt % 3;
        const uint32_t kBase = ksU + (uint32_t)st * KVSTG;
        const uint32_t vBase = vsU + (uint32_t)st * KVSTG;

        float s[8][4];
#pragma unroll
        for (int nt = 0; nt < 8; nt++)
#pragma unroll
            for (int v = 0; v < 4; v++) s[nt][v] = 0.f;

#pragma unroll
        for (int step = 0; step < 4; step++) {
#pragma unroll
            for (int np = 0; np < 4; np++) {
                uint32_t bb[4];
                ldsm4(bb, kBase + (uint32_t)((np * 16 + kb_row) * ST + step * 16 + kb_col) * 2);
                mma_f16(s[2 * np],     qf[step], bb[0], bb[1]);
                mma_f16(s[2 * np + 1], qf[step], bb[2], bb[3]);
            }
        }

        if (kt >= 2 * qt) {
#pragma unroll
            for (int nt = 0; nt < 8; nt++) {
                const int col = kt * 64 + nt * 8 + 2 * lq;
                if (col     > qrow0) s[nt][0] = -1e30f;
                if (col + 1 > qrow0) s[nt][1] = -1e30f;
                if (col     > qrow1) s[nt][2] = -1e30f;
                if (col + 1 > qrow1) s[nt][3] = -1e30f;
            }
        }

        float mx0 = -1e30f, mx1 = -1e30f;
#pragma unroll
        for (int nt = 0; nt < 8; nt++) {
            mx0 = fmaxf(mx0, fmaxf(s[nt][0], s[nt][1]));
            mx1 = fmaxf(mx1, fmaxf(s[nt][2], s[nt][3]));
        }
        __half2 mxh = __float22half2_rn(make_float2(mx0, mx1));
#pragma unroll
        for (int off = 1; off < 4; off <<= 1) {
            uint32_t mu = *(uint32_t*)&mxh;
            uint32_t ou = __shfl_xor_sync(0xffffffffu, mu, off);
            mxh = __hmax2(mxh, *(__half2*)&ou);
        }
        float2 mxf = __half22float2(mxh);
        const float mn0 = fmaxf(mrow0, mxf.x);
        const float mn1 = fmaxf(mrow1, mxf.y);
        const float corr0 = ex2(mrow0 - mn0);
        const float corr1 = ex2(mrow1 - mn1);
        mrow0 = mn0;
        mrow1 = mn1;

        uint32_t pf[4][4];
#pragma unroll
        for (int s4 = 0; s4 < 4; s4++) {
            pf[s4][0] = ex2h2(s[2 * s4][0] - mn0,     s[2 * s4][1] - mn0);
            pf[s4][1] = ex2h2(s[2 * s4][2] - mn1,     s[2 * s4][3] - mn1);
            pf[s4][2] = ex2h2(s[2 * s4 + 1][0] - mn0, s[2 * s4 + 1][1] - mn0);
            pf[s4][3] = ex2h2(s[2 * s4 + 1][2] - mn1, s[2 * s4 + 1][3] - mn1);
        }

#pragma unroll
        for (int nt = 0; nt < 8; nt++) {
            o[nt][0] *= corr0;
            o[nt][1] *= corr0;
            o[nt][2] *= corr1;
            o[nt][3] *= corr1;
        }
        osum[0] *= corr0;
        osum[1] *= corr0;
        osum[2] *= corr1;
        osum[3] *= corr1;

#pragma unroll
        for (int step = 0; step < 4; step++) {
#pragma unroll
            for (int np = 0; np < 4; np++) {
                uint32_t bb[4];
                ldsm4t(bb, vBase + (uint32_t)((step * 16 + vb_row) * ST + np * 16 + vb_col) * 2);
                mma_f16(o[2 * np],     pf[step], bb[0], bb[1]);
                mma_f16(o[2 * np + 1], pf[step], bb[2], bb[3]);
            }
            mma_f16(osum, pf[step], ONES_H2, ONES_H2);
        }
    }

    const int b = bh >> 4;
    const int h = bh & 15;
    const float inv0 = 1.f / osum[0];
    const float inv1 = 1.f / osum[2];
    const int srow = qt * 128 + wid * 16 + lr;
#pragma unroll
    for (int nt = 0; nt < 8; nt++) {
        const int d = nt * 8 + 2 * lq;
        __half2 p0 = __float22half2_rn(make_float2(o[nt][0] * inv0, o[nt][1] * inv0));
        __half2 p1 = __float22half2_rn(make_float2(o[nt][2] * inv1, o[nt][3] * inv1));
        *(uint32_t*)&ctx[(size_t)(b * NS + srow) * NDM + h * 64 + d] = *(uint32_t*)&p0;
        *(uint32_t*)&ctx[(size_t)(b * NS + srow + 8) * NDM + h * 64 + d] = *(uint32_t*)&p1;
    }
}

// ---------------------------------------------------------------------------
// LayerNorm (residual already folded in by gemm_out), in-place on out.
// ---------------------------------------------------------------------------
__global__ __launch_bounds__(256) void ln_kernel(const float* __restrict__ gamma,
                                                 const float* __restrict__ beta,
                                                 float* __restrict__ out) {
    __shared__ float rs[8], rq[8], fin[2];
    const int row = blockIdx.x;
    const int tid = threadIdx.x;
    const int c   = tid << 2;

    float4 x4 = *(const float4*)(out + (size_t)row * NDM + c);
    const float x0 = x4.x, x1 = x4.y, x2 = x4.z, x3 = x4.w;
    float s  = x0 + x1 + x2 + x3;
    float sq = x0 * x0 + x1 * x1 + x2 * x2 + x3 * x3;
#pragma unroll
    for (int off = 16; off; off >>= 1) {
        s  += __shfl_xor_sync(0xffffffffu, s, off);
        sq += __shfl_xor_sync(0xffffffffu, sq, off);
    }
    const int wid = tid >> 5, lane = tid & 31;
    if (lane == 0) { rs[wid] = s; rq[wid] = sq; }
    __syncthreads();
    if (tid == 0) {
        float a = 0.f, b2 = 0.f;
#pragma unroll
        for (int i = 0; i < 8; i++) { a += rs[i]; b2 += rq[i]; }
        fin[0] = a;
        fin[1] = b2;
    }
    __syncthreads();
    const float mu   = fin[0] * (1.0f / NDM);
    const float var  = fin[1] * (1.0f / NDM) - mu * mu;
    const float rstd = rsqrtf(var + 1e-5f);

    float4 g4 = *(const float4*)(gamma + c);
    float4 b4 = *(const float4*)(beta + c);
    float4 r;
    r.x = (x0 - mu) * rstd * g4.x + b4.x;
    r.y = (x1 - mu) * rstd * g4.y + b4.y;
    r.z = (x2 - mu) * rstd * g4.z + b4.z;
    r.w = (x3 - mu) * rstd * g4.w + b4.w;
    *(float4*)(out + (size_t)row * NDM + c) = r;
}

// ---------------------------------------------------------------------------
// Launch
// ---------------------------------------------------------------------------
extern "C" void kernel_launch(void* const* d_in, const int* in_sizes, int n_in,
                              void* d_out, int out_size) {
    const float* Q     = (const float*)d_in[0];
    const float* K     = (const float*)d_in[1];
    const float* V     = (const float*)d_in[2];
    const float* W_Q   = (const float*)d_in[3];
    const float* W_K   = (const float*)d_in[4];
    const float* W_V   = (const float*)d_in[5];
    const float* W_O   = (const float*)d_in[6];
    const float* gamma = (const float*)d_in[7];
    const float* beta  = (const float*)d_in[8];
    float* out = (float*)d_out;

    __half *qh, *kh, *vh, *ctxh, *wtq, *wtk, *wtv, *wto;
    cudaGetSymbolAddress((void**)&qh,   g_Qh);
    cudaGetSymbolAddress((void**)&kh,   g_Kh);
    cudaGetSymbolAddress((void**)&vh,   g_Vh);
    cudaGetSymbolAddress((void**)&ctxh, g_ctxh);
    cudaGetSymbolAddress((void**)&wtq,  g_WTq);
    cudaGetSymbolAddress((void**)&wtk,  g_WTk);
    cudaGetSymbolAddress((void**)&wtv,  g_WTv);
    cudaGetSymbolAddress((void**)&wto,  g_WTo);

    cudaFuncSetAttribute(attn_h, cudaFuncAttributeMaxDynamicSharedMemorySize,
                         ATTN_SMEM_BYTES);
    cudaFuncSetAttribute(gemm_qkv, cudaFuncAttributeMaxDynamicSharedMemorySize,
                         QKV_SMEM);
    cudaFuncSetAttribute(gemm_out, cudaFuncAttributeMaxDynamicSharedMemorySize,
                         OUT_SMEM);

    // weight transposes (fp32 -> fp16 W^T)
    wtrans4_kernel<<<dim3(32, 32, 4), 256>>>(W_Q, W_K, W_V, W_O, wtq, wtk, wtv, wto);

    // QKV projections straight from fp32 inputs (Q pre-scaled by 0.125*log2e)
    gemm_qkv<<<dim3(NDM / 128, NM / 128, 3), 256, QKV_SMEM>>>(
        Q, K, V, wtq, wtk, wtv, qh, kh, vh);

    // attention (fp16, register P, MMA row-sums, 3-stage KV), writes fp16 ctx
    attn_h<<<dim3(NS / 128, NB * NH), 256, ATTN_SMEM_BYTES>>>(qh, kh, vh, ctxh);

    // output projection + fused residual, then LN
    gemm_out<<<dim3(NDM / 128, NM / 128), 128, OUT_SMEM>>>(ctxh, wto, out, Q);
    ln_kernel<<<NM, 256>>>(gamma, beta, out);
}

// round 14
// speedup vs baseline: 1.0112x; 1.0112x over previous
#include <cuda_runtime.h>
#include <cuda_fp16.h>
#include <cstdint>

// Problem constants
#define NB   4
#define NS   2048
#define NDM  1024
#define NH   16
#define NM   (NB * NS)      // 8192 rows

// ---------------------------------------------------------------------------
// Device scratch
// ---------------------------------------------------------------------------
__device__ __half g_Qh[NB * NH * NS * 64];   // fp16 heads [B,H,S,64] (Q pre-scaled)
__device__ __half g_Kh[NB * NH * NS * 64];
__device__ __half g_Vh[NB * NH * NS * 64];
__device__ __half g_ctxh[NM * NDM];          // fp16 ctx [B*S, H*Dv]

__device__ __half g_WTq[NDM * NDM];          // fp16 W^T [n][k]
__device__ __half g_WTk[NDM * NDM];
__device__ __half g_WTv[NDM * NDM];
__device__ __half g_WTo[NDM * NDM];

// scale folded into Q heads: 1/sqrt(64) * log2(e)
#define QSCALE 0.18033688011112042f
#define ONES_H2 0x3C003C00u      // half2(1.0, 1.0)

// ---------------------------------------------------------------------------
// mma / ldmatrix / cp.async helpers
// ---------------------------------------------------------------------------
__device__ __forceinline__ uint32_t smem_u32(const void* p) {
    uint32_t a;
    asm("{ .reg .u64 t; cvta.to.shared.u64 t, %1; cvt.u32.u64 %0, t; }"
        : "=r"(a) : "l"(p));
    return a;
}

__device__ __forceinline__ void ldsm4(uint32_t r[4], uint32_t addr) {
    asm volatile("ldmatrix.sync.aligned.m8n8.x4.shared.b16 {%0,%1,%2,%3}, [%4];"
                 : "=r"(r[0]), "=r"(r[1]), "=r"(r[2]), "=r"(r[3]) : "r"(addr));
}

__device__ __forceinline__ void ldsm4t(uint32_t r[4], uint32_t addr) {
    asm volatile("ldmatrix.sync.aligned.m8n8.x4.trans.shared.b16 {%0,%1,%2,%3}, [%4];"
                 : "=r"(r[0]), "=r"(r[1]), "=r"(r[2]), "=r"(r[3]) : "r"(addr));
}

__device__ __forceinline__ void mma_f16(float c[4], const uint32_t a[4],
                                        uint32_t b0, uint32_t b1) {
    asm volatile(
        "mma.sync.aligned.m16n8k16.row.col.f32.f16.f16.f32 "
        "{%0,%1,%2,%3}, {%4,%5,%6,%7}, {%8,%9}, {%0,%1,%2,%3};"
        : "+f"(c[0]), "+f"(c[1]), "+f"(c[2]), "+f"(c[3])
        : "r"(a[0]), "r"(a[1]), "r"(a[2]), "r"(a[3]), "r"(b0), "r"(b1));
}

__device__ __forceinline__ void cp16(uint32_t dst, const void* src) {
    asm volatile("cp.async.cg.shared.global [%0], [%1], 16;" :: "r"(dst), "l"(src));
}
#define CP_COMMIT() asm volatile("cp.async.commit_group;")
#define CP_WAIT0()  asm volatile("cp.async.wait_group 0;")
#define CP_WAIT3()  asm volatile("cp.async.wait_group 3;")

__device__ __forceinline__ float ex2(float x) {
    float r;
    asm("ex2.approx.f32 %0, %1;" : "=f"(r) : "f"(x));
    return r;
}

__device__ __forceinline__ uint32_t ex2h2(float a, float b) {
    __half2 h = __float22half2_rn(make_float2(a, b));
    uint32_t u = *(uint32_t*)&h;
    asm("ex2.approx.f16x2 %0, %0;" : "+r"(u));
    return u;
}

// ---------------------------------------------------------------------------
// Weight transpose: W [k][n] fp32 -> WT [n][k] fp16, batched over z
// ---------------------------------------------------------------------------
__global__ __launch_bounds__(256) void wtrans4_kernel(const float* __restrict__ w0,
                                                      const float* __restrict__ w1,
                                                      const float* __restrict__ w2,
                                                      const float* __restrict__ w3,
                                                      __half* t0, __half* t1,
                                                      __half* t2, __half* t3) {
    __shared__ float t[32][33];
    const int z = blockIdx.z;
    const float* W = (z == 0) ? w0 : (z == 1) ? w1 : (z == 2) ? w2 : w3;
    __half* WT = (z == 0) ? t0 : (z == 1) ? t1 : (z == 2) ? t2 : t3;
    const int tx = threadIdx.x & 31;
    const int ty = threadIdx.x >> 5;
    const int bn = blockIdx.x * 32;
    const int bk = blockIdx.y * 32;
#pragma unroll
    for (int i = 0; i < 4; i++)
        t[ty + 8 * i][tx] = W[(size_t)(bk + ty + 8 * i) * NDM + bn + tx];
    __syncthreads();
#pragma unroll
    for (int i = 0; i < 4; i++)
        WT[(size_t)(bn + ty + 8 * i) * NDM + bk + tx] =
            __float2half(t[tx][ty + 8 * i]);
}

// ---------------------------------------------------------------------------
// Shared GEMM constants (BK=32 tiles)
// ---------------------------------------------------------------------------
#define GW 20                        // 32-bit words per smem row
#define GSTG 10240                   // bytes per stage (128 rows)
#define QKV_SMEM (2 * GSTG + 5 * GSTG)   // A 2-stage + B 5-stage = 71680
#define OUT_SMEM (5 * GSTG + 5 * GSTG)   // A+B 5-stage = 102400

// ---------------------------------------------------------------------------
// QKV projection: 256 threads, warp tile 32x64.
// A fp32 direct (LDG+cvt+STS, 2-stage), B fp16 cp.async 5-stage.
// Epilogue: fp16 heads [B,H,S,64], scaled.
// ---------------------------------------------------------------------------
__global__ __launch_bounds__(256, 2) void gemm_qkv(const float* __restrict__ Qf,
                                                   const float* __restrict__ Kf,
                                                   const float* __restrict__ Vf,
                                                   const __half* __restrict__ wtq,
                                                   const __half* __restrict__ wtk,
                                                   const __half* __restrict__ wtv,
                                                   __half* qh, __half* kh, __half* vh) {
    extern __shared__ __align__(16) uint8_t gsm[];
    const uint32_t base = smem_u32(gsm);

    const int z = blockIdx.z;
    const float* A   = (z == 0) ? Qf : (z == 1) ? Kf : Vf;
    const __half* BT = (z == 0) ? wtq : (z == 1) ? wtk : wtv;
    __half* C        = (z == 0) ? qh : (z == 1) ? kh : vh;
    const float scale = (z == 0) ? QSCALE : 1.0f;

    const int tid  = threadIdx.x;
    const int lane = tid & 31;
    const int wid  = tid >> 5;
    const int lr   = lane >> 2;
    const int lq   = lane & 3;
    const int wm0  = (wid & 3) * 32;
    const int wn0  = (wid >> 2) * 64;
    const int m0   = blockIdx.y * 128;
    const int n0   = blockIdx.x * 128;

    const int a_row = wm0 + (lane & 7) + (lane & 8);
    const int a_wrd = (lane >> 4) << 2;
    const int b_row = wn0 + (lane & 7) + ((lane & 16) >> 1);
    const int b_wrd = (lane & 8) ? 4 : 0;

    const int br = tid >> 2;          // 0..63
    const int bc = tid & 3;
    const uint8_t* Bg = (const uint8_t*)BT + (size_t)n0 * 2048 + bc * 16;

    auto cpB = [&](int c) {
        const uint32_t bB = base + 2 * GSTG + (uint32_t)(c % 5) * GSTG;
        const size_t koff = (size_t)c * 64;
#pragma unroll
        for (int i = 0; i < 2; i++) {
            const uint32_t so = (uint32_t)((br + 64 * i) * GW + bc * 4) * 4;
            cp16(bB + so, Bg + (size_t)(br + 64 * i) * 2048 + koff);
        }
        CP_COMMIT();
    };

    auto ldgA = [&](int c, float4 ra[4]) {
#pragma unroll
        for (int i = 0; i < 4; i++) {
            const int gidx = tid + 256 * i;
            const int r = gidx >> 3, seg = gidx & 7;
            ra[i] = *(const float4*)(A + (size_t)(m0 + r) * NDM + c * 32 + seg * 4);
        }
    };
    auto stsA = [&](int c, const float4 ra[4]) {
        const uint32_t off = (uint32_t)(c & 1) * GSTG;
#pragma unroll
        for (int i = 0; i < 4; i++) {
            const int gidx = tid + 256 * i;
            const int r = gidx >> 3, seg = gidx & 7;
            __half2 h0 = __float22half2_rn(make_float2(ra[i].x, ra[i].y));
            __half2 h1 = __float22half2_rn(make_float2(ra[i].z, ra[i].w));
            uint2 u = make_uint2(*(uint32_t*)&h0, *(uint32_t*)&h1);
            *(uint2*)(gsm + off + (uint32_t)(r * GW + seg * 2) * 4) = u;
        }
    };

    float acc[2][8][4];
#pragma unroll
    for (int mi = 0; mi < 2; mi++)
#pragma unroll
        for (int nt = 0; nt < 8; nt++)
#pragma unroll
            for (int v = 0; v < 4; v++) acc[mi][nt][v] = 0.f;

    float4 ra[4];
    ldgA(0, ra);
    cpB(0); cpB(1); cpB(2); cpB(3);
    stsA(0, ra);
    ldgA(1, ra);

    for (int c = 0; c < 32; c++) {
        if (c < 28) CP_WAIT3(); else CP_WAIT0();
        __syncthreads();
        if (c + 4 < 32) cpB(c + 4);
        if (c + 1 < 32) stsA(c + 1, ra);
        if (c + 2 < 32) ldgA(c + 2, ra);

        const uint32_t aB = base + (uint32_t)(c & 1) * GSTG;
        const uint32_t bB = base + 2 * GSTG + (uint32_t)(c % 5) * GSTG;

#pragma unroll
        for (int s = 0; s < 2; s++) {
            uint32_t a[2][4];
            ldsm4(a[0], aB + (uint32_t)((a_row)*GW + s * 8 + a_wrd) * 4);
            ldsm4(a[1], aB + (uint32_t)((a_row + 16) * GW + s * 8 + a_wrd) * 4);
#pragma unroll
            for (int np = 0; np < 4; np++) {
                uint32_t bb[4];
                ldsm4(bb, bB + (uint32_t)((b_row + np * 16) * GW + s * 8 + b_wrd) * 4);
                mma_f16(acc[0][2 * np],     a[0], bb[0], bb[1]);
                mma_f16(acc[1][2 * np],     a[1], bb[0], bb[1]);
                mma_f16(acc[0][2 * np + 1], a[0], bb[2], bb[3]);
                mma_f16(acc[1][2 * np + 1], a[1], bb[2], bb[3]);
            }
        }
    }

#pragma unroll
    for (int mi = 0; mi < 2; mi++) {
        const int row0 = m0 + wm0 + mi * 16 + lr;
#pragma unroll
        for (int nt = 0; nt < 8; nt++) {
            const int col = wn0 + nt * 8 + 2 * lq;
            __half2 v0 = __float22half2_rn(
                make_float2(acc[mi][nt][0] * scale, acc[mi][nt][1] * scale));
            __half2 v1 = __float22half2_rn(
                make_float2(acc[mi][nt][2] * scale, acc[mi][nt][3] * scale));
            const int gcol = n0 + col;
            const int h = gcol >> 6, d = gcol & 63;
            const int b0i = row0 >> 11, s0 = row0 & 2047;
            *(uint32_t*)&C[(size_t)((b0i * NH + h) * NS + s0) * 64 + d] = *(uint32_t*)&v0;
            const int row1 = row0 + 8;
            const int b1i = row1 >> 11, s1 = row1 & 2047;
            *(uint32_t*)&C[(size_t)((b1i * NH + h) * NS + s1) * 64 + d] = *(uint32_t*)&v1;
        }
    }
}

// ---------------------------------------------------------------------------
// Output projection: 128 threads, warp tile 64x64, BK=32, 5-stage cp.async.
// Zero register staging. Epilogue: fp32 out + residual.
// ---------------------------------------------------------------------------
__global__ __launch_bounds__(128, 2) void gemm_out(const __half* __restrict__ A,
                                                   const __half* __restrict__ BT,
                                                   float* __restrict__ C,
                                                   const float* __restrict__ resid) {
    extern __shared__ __align__(16) uint8_t gsm[];
    const uint32_t base = smem_u32(gsm);

    const int tid  = threadIdx.x;
    const int lane = tid & 31;
    const int wid  = tid >> 5;
    const int lr   = lane >> 2;
    const int lq   = lane & 3;
    const int wm0  = (wid & 1) * 64;
    const int wn0  = (wid >> 1) * 64;
    const int m0   = blockIdx.y * 128;
    const int n0   = blockIdx.x * 128;

    const int a_row = wm0 + (lane & 7) + (lane & 8);
    const int a_wrd = (lane >> 4) << 2;
    const int b_row = wn0 + (lane & 7) + ((lane & 16) >> 1);
    const int b_wrd = (lane & 8) ? 4 : 0;

    const uint8_t* Ag = (const uint8_t*)A + (size_t)m0 * 2048;
    const uint8_t* Bg = (const uint8_t*)BT + (size_t)n0 * 2048;

    auto prefetch = [&](int c) {
        const int stg = c % 5;
        const uint32_t aB = base + (uint32_t)stg * GSTG;
        const uint32_t bB = base + 5 * GSTG + (uint32_t)stg * GSTG;
        const size_t koff = (size_t)c * 64;
#pragma unroll
        for (int i = 0; i < 4; i++) {
            const int idx = tid + 128 * i;
            const int r = idx >> 2, seg = idx & 3;
            const uint32_t so = (uint32_t)(r * GW + seg * 4) * 4;
            cp16(aB + so, Ag + (size_t)r * 2048 + koff + seg * 16);
            cp16(bB + so, Bg + (size_t)r * 2048 + koff + seg * 16);
        }
        CP_COMMIT();
    };

    float acc[4][8][4];
#pragma unroll
    for (int mi = 0; mi < 4; mi++)
#pragma unroll
        for (int nt = 0; nt < 8; nt++)
#pragma unroll
            for (int v = 0; v < 4; v++) acc[mi][nt][v] = 0.f;

    prefetch(0);
    prefetch(1);
    prefetch(2);
    prefetch(3);

    for (int c = 0; c < 32; c++) {
        if (c < 28) CP_WAIT3(); else CP_WAIT0();
        __syncthreads();                 // all warps done with stage (c-1)%5
        if (c + 4 < 32) prefetch(c + 4); // overwrites stage (c-1)%5 — safe

        const int stg = c % 5;
        const uint32_t aB = base + (uint32_t)stg * GSTG;
        const uint32_t bB = base + 5 * GSTG + (uint32_t)stg * GSTG;

#pragma unroll
        for (int s = 0; s < 2; s++) {
            uint32_t a[4][4];
#pragma unroll
            for (int mi = 0; mi < 4; mi++)
                ldsm4(a[mi], aB + (uint32_t)((a_row + mi * 16) * GW + s * 8 + a_wrd) * 4);
#pragma unroll
            for (int np = 0; np < 4; np++) {
                uint32_t bb[4];
                ldsm4(bb, bB + (uint32_t)((b_row + np * 16) * GW + s * 8 + b_wrd) * 4);
#pragma unroll
                for (int mi = 0; mi < 4; mi++) {
                    mma_f16(acc[mi][2 * np],     a[mi], bb[0], bb[1]);
                    mma_f16(acc[mi][2 * np + 1], a[mi], bb[2], bb[3]);
                }
            }
        }
    }

#pragma unroll
    for (int mi = 0; mi < 4; mi++) {
        const int row0 = m0 + wm0 + mi * 16 + lr;
#pragma unroll
        for (int nt = 0; nt < 8; nt++) {
            const int col = n0 + wn0 + nt * 8 + 2 * lq;
            float2 q0 = *(const float2*)&resid[(size_t)row0 * NDM + col];
            float2 q1 = *(const float2*)&resid[(size_t)(row0 + 8) * NDM + col];
            *(float2*)&C[(size_t)row0 * NDM + col] =
                make_float2(acc[mi][nt][0] + q0.x, acc[mi][nt][1] + q0.y);
            *(float2*)&C[(size_t)(row0 + 8) * NDM + col] =
                make_float2(acc[mi][nt][2] + q1.x, acc[mi][nt][3] + q1.y);
        }
    }
}

// ---------------------------------------------------------------------------
// Flash attention, causal, fp16 mma m16n8k16 (exact R12: 2-stage K/V ring).
// ---------------------------------------------------------------------------
#define ST 72
#define ATTN_SMEM_BYTES ((128 + 2 * 64 + 2 * 64) * ST * 2)   // 55296

__global__ __launch_bounds__(256, 2) void attn_h(const __half* __restrict__ Qh,
                                                 const __half* __restrict__ Kh,
                                                 const __half* __restrict__ Vh,
                                                 __half* __restrict__ ctx) {
    extern __shared__ __half smh[];
    __half* Qs = smh;
    __half* Ks0 = Qs + 128 * ST;
    __half* Vs0 = Ks0 + 2 * 64 * ST;
    const uint32_t qsU = smem_u32(Qs);
    const uint32_t ksU = smem_u32(Ks0);
    const uint32_t vsU = smem_u32(Vs0);
    const uint32_t KVSTG = 64 * ST * 2;

    const int tid  = threadIdx.x;
    const int lane = tid & 31;
    const int wid  = tid >> 5;
    const int lr   = lane >> 2;
    const int lq   = lane & 3;

    const int qt = gridDim.x - 1 - blockIdx.x;
    const int bh = blockIdx.y;

    const __half* Qb = Qh + (size_t)bh * NS * 64;
    const __half* Kb = Kh + (size_t)bh * NS * 64;
    const __half* Vb = Vh + (size_t)bh * NS * 64;

    auto prefetch = [&](int kt, int st) {
#pragma unroll
        for (int i = 0; i < 2; i++) {
            const int idx = tid + 256 * i;
            const int r = idx >> 3, cu = idx & 7;
            cp16(ksU + (uint32_t)st * KVSTG + (uint32_t)(r * ST + cu * 8) * 2,
                 Kb + (size_t)(kt * 64 + r) * 64 + cu * 8);
            cp16(vsU + (uint32_t)st * KVSTG + (uint32_t)(r * ST + cu * 8) * 2,
                 Vb + (size_t)(kt * 64 + r) * 64 + cu * 8);
        }
        CP_COMMIT();
    };

    prefetch(0, 0);
#pragma unroll
    for (int i = 0; i < 4; i++) {
        const int idx = tid + 256 * i;
        const int r = idx >> 3, cu = idx & 7;
        *(uint4*)&Qs[r * ST + cu * 8] =
            *(const uint4*)(Qb + (size_t)(qt * 128 + r) * 64 + cu * 8);
    }
    __syncthreads();

    uint32_t qf[4][4];
    {
        const int arow = wid * 16 + (lane & 7) + (lane & 8);
        const int acol = (lane & 16) >> 1;
#pragma unroll
        for (int s = 0; s < 4; s++)
            ldsm4(qf[s], qsU + (uint32_t)(arow * ST + s * 16 + acol) * 2);
    }

    float o[8][4];
#pragma unroll
    for (int nt = 0; nt < 8; nt++)
#pragma unroll
        for (int v = 0; v < 4; v++) o[nt][v] = 0.f;
    float osum[4] = {0.f, 0.f, 0.f, 0.f};
    float mrow0 = -1e30f, mrow1 = -1e30f;

    const int qrow0 = qt * 128 + wid * 16 + lr;
    const int qrow1 = qrow0 + 8;
    const int ktmax = 2 * qt + 1;

    const int kb_row = (lane & 7) + ((lane & 16) >> 1);
    const int kb_col = (lane & 8) ? 8 : 0;
    const int vb_row = (lane & 7) + (lane & 8);
    const int vb_col = (lane & 16) >> 1;

    for (int kt = 0; kt <= ktmax; kt++) {
        const int st = kt & 1;
        CP_WAIT0();
        __syncthreads();
        if (kt < ktmax) prefetch(kt + 1, st ^ 1);

        const uint32_t kBase = ksU + (uint32_t)st * KVSTG;
        const uint32_t vBase = vsU + (uint32_t)st * KVSTG;

        float s[8][4];
#pragma unroll
        for (int nt = 0; nt < 8; nt++)
#pragma unroll
            for (int v = 0; v < 4; v++) s[nt][v] = 0.f;

#pragma unroll
        for (int step = 0; step < 4; step++) {
#pragma unroll
            for (int np = 0; np < 4; np++) {
                uint32_t bb[4];
                ldsm4(bb, kBase + (uint32_t)((np * 16 + kb_row) * ST + step * 16 + kb_col) * 2);
                mma_f16(s[2 * np],     qf[step], bb[0], bb[1]);
                mma_f16(s[2 * np + 1], qf[step], bb[2], bb[3]);
            }
        }

        if (kt >= 2 * qt) {
#pragma unroll
            for (int nt = 0; nt < 8; nt++) {
                const int col = kt * 64 + nt * 8 + 2 * lq;
                if (col     > qrow0) s[nt][0] = -1e30f;
                if (col + 1 > qrow0) s[nt][1] = -1e30f;
                if (col     > qrow1) s[nt][2] = -1e30f;
                if (col + 1 > qrow1) s[nt][3] = -1e30f;
            }
        }

        float mx0 = -1e30f, mx1 = -1e30f;
#pragma unroll
        for (int nt = 0; nt < 8; nt++) {
            mx0 = fmaxf(mx0, fmaxf(s[nt][0], s[nt][1]));
            mx1 = fmaxf(mx1, fmaxf(s[nt][2], s[nt][3]));
        }
        __half2 mxh = __float22half2_rn(make_float2(mx0, mx1));
#pragma unroll
        for (int off = 1; off < 4; off <<= 1) {
            uint32_t mu = *(uint32_t*)&mxh;
            uint32_t ou = __shfl_xor_sync(0xffffffffu, mu, off);
            mxh = __hmax2(mxh, *(__half2*)&ou);
        }
        float2 mxf = __half22float2(mxh);
        const float mn0 = fmaxf(mrow0, mxf.x);
        const float mn1 = fmaxf(mrow1, mxf.y);
        const float corr0 = ex2(mrow0 - mn0);
        const float corr1 = ex2(mrow1 - mn1);
        mrow0 = mn0;
        mrow1 = mn1;

        uint32_t pf[4][4];
#pragma unroll
        for (int s4 = 0; s4 < 4; s4++) {
            pf[s4][0] = ex2h2(s[2 * s4][0] - mn0,     s[2 * s4][1] - mn0);
            pf[s4][1] = ex2h2(s[2 * s4][2] - mn1,     s[2 * s4][3] - mn1);
            pf[s4][2] = ex2h2(s[2 * s4 + 1][0] - mn0, s[2 * s4 + 1][1] - mn0);
            pf[s4][3] = ex2h2(s[2 * s4 + 1][2] - mn1, s[2 * s4 + 1][3] - mn1);
        }

#pragma unroll
        for (int nt = 0; nt < 8; nt++) {
            o[nt][0] *= corr0;
            o[nt][1] *= corr0;
            o[nt][2] *= corr1;
            o[nt][3] *= corr1;
        }
        osum[0] *= corr0;
        osum[1] *= corr0;
        osum[2] *= corr1;
        osum[3] *= corr1;

#pragma unroll
        for (int step = 0; step < 4; step++) {
#pragma unroll
            for (int np = 0; np < 4; np++) {
                uint32_t bb[4];
                ldsm4t(bb, vBase + (uint32_t)((step * 16 + vb_row) * ST + np * 16 + vb_col) * 2);
                mma_f16(o[2 * np],     pf[step], bb[0], bb[1]);
                mma_f16(o[2 * np + 1], pf[step], bb[2], bb[3]);
            }
            mma_f16(osum, pf[step], ONES_H2, ONES_H2);
        }
    }

    const int b = bh >> 4;
    const int h = bh & 15;
    const float inv0 = 1.f / osum[0];
    const float inv1 = 1.f / osum[2];
    const int srow = qt * 128 + wid * 16 + lr;
#pragma unroll
    for (int nt = 0; nt < 8; nt++) {
        const int d = nt * 8 + 2 * lq;
        __half2 p0 = __float22half2_rn(make_float2(o[nt][0] * inv0, o[nt][1] * inv0));
        __half2 p1 = __float22half2_rn(make_float2(o[nt][2] * inv1, o[nt][3] * inv1));
        *(uint32_t*)&ctx[(size_t)(b * NS + srow) * NDM + h * 64 + d] = *(uint32_t*)&p0;
        *(uint32_t*)&ctx[(size_t)(b * NS + srow + 8) * NDM + h * 64 + d] = *(uint32_t*)&p1;
    }
}

// ---------------------------------------------------------------------------
// LayerNorm (residual already folded in by gemm_out), in-place on out.
// ---------------------------------------------------------------------------
__global__ __launch_bounds__(256) void ln_kernel(const float* __restrict__ gamma,
                                                 const float* __restrict__ beta,
                                                 float* __restrict__ out) {
    __shared__ float rs[8], rq[8], fin[2];
    const int row = blockIdx.x;
    const int tid = threadIdx.x;
    const int c   = tid << 2;

    float4 x4 = *(const float4*)(out + (size_t)row * NDM + c);
    const float x0 = x4.x, x1 = x4.y, x2 = x4.z, x3 = x4.w;
    float s  = x0 + x1 + x2 + x3;
    float sq = x0 * x0 + x1 * x1 + x2 * x2 + x3 * x3;
#pragma unroll
    for (int off = 16; off; off >>= 1) {
        s  += __shfl_xor_sync(0xffffffffu, s, off);
        sq += __shfl_xor_sync(0xffffffffu, sq, off);
    }
    const int wid = tid >> 5, lane = tid & 31;
    if (lane == 0) { rs[wid] = s; rq[wid] = sq; }
    __syncthreads();
    if (tid == 0) {
        float a = 0.f, b2 = 0.f;
#pragma unroll
        for (int i = 0; i < 8; i++) { a += rs[i]; b2 += rq[i]; }
        fin[0] = a;
        fin[1] = b2;
    }
    __syncthreads();
    const float mu   = fin[0] * (1.0f / NDM);
    const float var  = fin[1] * (1.0f / NDM) - mu * mu;
    const float rstd = rsqrtf(var + 1e-5f);

    float4 g4 = *(const float4*)(gamma + c);
    float4 b4 = *(const float4*)(beta + c);
    float4 r;
    r.x = (x0 - mu) * rstd * g4.x + b4.x;
    r.y = (x1 - mu) * rstd * g4.y + b4.y;
    r.z = (x2 - mu) * rstd * g4.z + b4.z;
    r.w = (x3 - mu) * rstd * g4.w + b4.w;
    *(float4*)(out + (size_t)row * NDM + c) = r;
}

// ---------------------------------------------------------------------------
// Launch
// ---------------------------------------------------------------------------
extern "C" void kernel_launch(void* const* d_in, const int* in_sizes, int n_in,
                              void* d_out, int out_size) {
    const float* Q     = (const float*)d_in[0];
    const float* K     = (const float*)d_in[1];
    const float* V     = (const float*)d_in[2];
    const float* W_Q   = (const float*)d_in[3];
    const float* W_K   = (const float*)d_in[4];
    const float* W_V   = (const float*)d_in[5];
    const float* W_O   = (const float*)d_in[6];
    const float* gamma = (const float*)d_in[7];
    const float* beta  = (const float*)d_in[8];
    float* out = (float*)d_out;

    __half *qh, *kh, *vh, *ctxh, *wtq, *wtk, *wtv, *wto;
    cudaGetSymbolAddress((void**)&qh,   g_Qh);
    cudaGetSymbolAddress((void**)&kh,   g_Kh);
    cudaGetSymbolAddress((void**)&vh,   g_Vh);
    cudaGetSymbolAddress((void**)&ctxh, g_ctxh);
    cudaGetSymbolAddress((void**)&wtq,  g_WTq);
    cudaGetSymbolAddress((void**)&wtk,  g_WTk);
    cudaGetSymbolAddress((void**)&wtv,  g_WTv);
    cudaGetSymbolAddress((void**)&wto,  g_WTo);

    cudaFuncSetAttribute(attn_h, cudaFuncAttributeMaxDynamicSharedMemorySize,
                         ATTN_SMEM_BYTES);
    cudaFuncSetAttribute(gemm_qkv, cudaFuncAttributeMaxDynamicSharedMemorySize,
                         QKV_SMEM);
    cudaFuncSetAttribute(gemm_out, cudaFuncAttributeMaxDynamicSharedMemorySize,
                         OUT_SMEM);

    // weight transposes (fp32 -> fp16 W^T)
    wtrans4_kernel<<<dim3(32, 32, 4), 256>>>(W_Q, W_K, W_V, W_O, wtq, wtk, wtv, wto);

    // QKV projections straight from fp32 inputs (Q pre-scaled by 0.125*log2e)
    gemm_qkv<<<dim3(NDM / 128, NM / 128, 3), 256, QKV_SMEM>>>(
        Q, K, V, wtq, wtk, wtv, qh, kh, vh);

    // attention (fp16, register P, MMA row-sums), writes fp16 ctx
    attn_h<<<dim3(NS / 128, NB * NH), 256, ATTN_SMEM_BYTES>>>(qh, kh, vh, ctxh);

    // output projection + fused residual, then LN
    gemm_out<<<dim3(NDM / 128, NM / 128), 128, OUT_SMEM>>>(ctxh, wto, out, Q);
    ln_kernel<<<NM, 256>>>(gamma, beta, out);
}

// round 15
// speedup vs baseline: 1.0116x; 1.0004x over previous
#include <cuda_runtime.h>
#include <cuda_fp16.h>
#include <cstdint>

// Problem constants
#define NB   4
#define NS   2048
#define NDM  1024
#define NH   16
#define NM   (NB * NS)      // 8192 rows

// ---------------------------------------------------------------------------
// Device scratch
// ---------------------------------------------------------------------------
__device__ __half g_Qh[NB * NH * NS * 64];   // fp16 heads [B,H,S,64] (Q pre-scaled)
__device__ __half g_Kh[NB * NH * NS * 64];
__device__ __half g_Vh[NB * NH * NS * 64];
__device__ __half g_ctxh[NM * NDM];          // fp16 ctx [B*S, H*Dv]

__device__ __half g_WTq[NDM * NDM];          // fp16 W^T [n][k]
__device__ __half g_WTk[NDM * NDM];
__device__ __half g_WTv[NDM * NDM];
__device__ __half g_WTo[NDM * NDM];

// scale folded into Q heads: 1/sqrt(64) * log2(e)
#define QSCALE 0.18033688011112042f
#define ONES_H2 0x3C003C00u      // half2(1.0, 1.0)

// ---------------------------------------------------------------------------
// mma / ldmatrix / cp.async helpers
// ---------------------------------------------------------------------------
__device__ __forceinline__ uint32_t smem_u32(const void* p) {
    uint32_t a;
    asm("{ .reg .u64 t; cvta.to.shared.u64 t, %1; cvt.u32.u64 %0, t; }"
        : "=r"(a) : "l"(p));
    return a;
}

__device__ __forceinline__ void ldsm4(uint32_t r[4], uint32_t addr) {
    asm volatile("ldmatrix.sync.aligned.m8n8.x4.shared.b16 {%0,%1,%2,%3}, [%4];"
                 : "=r"(r[0]), "=r"(r[1]), "=r"(r[2]), "=r"(r[3]) : "r"(addr));
}

__device__ __forceinline__ void ldsm4t(uint32_t r[4], uint32_t addr) {
    asm volatile("ldmatrix.sync.aligned.m8n8.x4.trans.shared.b16 {%0,%1,%2,%3}, [%4];"
                 : "=r"(r[0]), "=r"(r[1]), "=r"(r[2]), "=r"(r[3]) : "r"(addr));
}

__device__ __forceinline__ void mma_f16(float c[4], const uint32_t a[4],
                                        uint32_t b0, uint32_t b1) {
    asm volatile(
        "mma.sync.aligned.m16n8k16.row.col.f32.f16.f16.f32 "
        "{%0,%1,%2,%3}, {%4,%5,%6,%7}, {%8,%9}, {%0,%1,%2,%3};"
        : "+f"(c[0]), "+f"(c[1]), "+f"(c[2]), "+f"(c[3])
        : "r"(a[0]), "r"(a[1]), "r"(a[2]), "r"(a[3]), "r"(b0), "r"(b1));
}

__device__ __forceinline__ void cp16(uint32_t dst, const void* src) {
    asm volatile("cp.async.cg.shared.global [%0], [%1], 16;" :: "r"(dst), "l"(src));
}
#define CP_COMMIT() asm volatile("cp.async.commit_group;")
#define CP_WAIT0()  asm volatile("cp.async.wait_group 0;")
#define CP_WAIT2()  asm volatile("cp.async.wait_group 2;")

__device__ __forceinline__ float ex2(float x) {
    float r;
    asm("ex2.approx.f32 %0, %1;" : "=f"(r) : "f"(x));
    return r;
}

__device__ __forceinline__ uint32_t ex2h2(float a, float b) {
    __half2 h = __float22half2_rn(make_float2(a, b));
    uint32_t u = *(uint32_t*)&h;
    asm("ex2.approx.f16x2 %0, %0;" : "+r"(u));
    return u;
}

// ---------------------------------------------------------------------------
// Weight transpose: W [k][n] fp32 -> WT [n][k] fp16, batched over z
// ---------------------------------------------------------------------------
__global__ __launch_bounds__(256) void wtrans4_kernel(const float* __restrict__ w0,
                                                      const float* __restrict__ w1,
                                                      const float* __restrict__ w2,
                                                      const float* __restrict__ w3,
                                                      __half* t0, __half* t1,
                                                      __half* t2, __half* t3) {
    __shared__ float t[32][33];
    const int z = blockIdx.z;
    const float* W = (z == 0) ? w0 : (z == 1) ? w1 : (z == 2) ? w2 : w3;
    __half* WT = (z == 0) ? t0 : (z == 1) ? t1 : (z == 2) ? t2 : t3;
    const int tx = threadIdx.x & 31;
    const int ty = threadIdx.x >> 5;
    const int bn = blockIdx.x * 32;
    const int bk = blockIdx.y * 32;
#pragma unroll
    for (int i = 0; i < 4; i++)
        t[ty + 8 * i][tx] = W[(size_t)(bk + ty + 8 * i) * NDM + bn + tx];
    __syncthreads();
#pragma unroll
    for (int i = 0; i < 4; i++)
        WT[(size_t)(bn + ty + 8 * i) * NDM + bk + tx] =
            __float2half(t[tx][ty + 8 * i]);
}

// ---------------------------------------------------------------------------
// Shared GEMM constants (R12 exact)
// ---------------------------------------------------------------------------
#define GW 20                        // 32-bit words per smem row
#define GSTG 10240                   // bytes per BK=32 stage (128 rows)
#define QKV_SMEM (2 * GSTG + 4 * GSTG)   // 61440
#define OUT_SMEM (4 * GSTG + 4 * GSTG)   // 81920

// ---------------------------------------------------------------------------
// QKV projection (R12 exact): 256 threads, warp tile 32x64.
// ---------------------------------------------------------------------------
__global__ __launch_bounds__(256, 2) void gemm_qkv(const float* __restrict__ Qf,
                                                   const float* __restrict__ Kf,
                                                   const float* __restrict__ Vf,
                                                   const __half* __restrict__ wtq,
                                                   const __half* __restrict__ wtk,
                                                   const __half* __restrict__ wtv,
                                                   __half* qh, __half* kh, __half* vh) {
    extern __shared__ __align__(16) uint8_t gsm[];
    const uint32_t base = smem_u32(gsm);

    const int z = blockIdx.z;
    const float* A   = (z == 0) ? Qf : (z == 1) ? Kf : Vf;
    const __half* BT = (z == 0) ? wtq : (z == 1) ? wtk : wtv;
    __half* C        = (z == 0) ? qh : (z == 1) ? kh : vh;
    const float scale = (z == 0) ? QSCALE : 1.0f;

    const int tid  = threadIdx.x;
    const int lane = tid & 31;
    const int wid  = tid >> 5;
    const int lr   = lane >> 2;
    const int lq   = lane & 3;
    const int wm0  = (wid & 3) * 32;
    const int wn0  = (wid >> 2) * 64;
    const int m0   = blockIdx.y * 128;
    const int n0   = blockIdx.x * 128;

    const int a_row = wm0 + (lane & 7) + (lane & 8);
    const int a_wrd = (lane >> 4) << 2;
    const int b_row = wn0 + (lane & 7) + ((lane & 16) >> 1);
    const int b_wrd = (lane & 8) ? 4 : 0;

    const int br = tid >> 2;
    const int bc = tid & 3;
    const uint8_t* Bg = (const uint8_t*)BT + (size_t)n0 * 2048 + bc * 16;

    auto cpB = [&](int c) {
        const uint32_t bB = base + 2 * GSTG + (uint32_t)(c & 3) * GSTG;
        const size_t koff = (size_t)c * 64;
#pragma unroll
        for (int i = 0; i < 2; i++) {
            const uint32_t so = (uint32_t)((br + 64 * i) * GW + bc * 4) * 4;
            cp16(bB + so, Bg + (size_t)(br + 64 * i) * 2048 + koff);
        }
        CP_COMMIT();
    };

    auto ldgA = [&](int c, float4 ra[4]) {
#pragma unroll
        for (int i = 0; i < 4; i++) {
            const int gidx = tid + 256 * i;
            const int r = gidx >> 3, seg = gidx & 7;
            ra[i] = *(const float4*)(A + (size_t)(m0 + r) * NDM + c * 32 + seg * 4);
        }
    };
    auto stsA = [&](int c, const float4 ra[4]) {
        const uint32_t off = (uint32_t)(c & 1) * GSTG;
#pragma unroll
        for (int i = 0; i < 4; i++) {
            const int gidx = tid + 256 * i;
            const int r = gidx >> 3, seg = gidx & 7;
            __half2 h0 = __float22half2_rn(make_float2(ra[i].x, ra[i].y));
            __half2 h1 = __float22half2_rn(make_float2(ra[i].z, ra[i].w));
            uint2 u = make_uint2(*(uint32_t*)&h0, *(uint32_t*)&h1);
            *(uint2*)(gsm + off + (uint32_t)(r * GW + seg * 2) * 4) = u;
        }
    };

    float acc[2][8][4];
#pragma unroll
    for (int mi = 0; mi < 2; mi++)
#pragma unroll
        for (int nt = 0; nt < 8; nt++)
#pragma unroll
            for (int v = 0; v < 4; v++) acc[mi][nt][v] = 0.f;

    float4 ra[4];
    ldgA(0, ra);
    cpB(0); cpB(1); cpB(2);
    stsA(0, ra);
    ldgA(1, ra);

    for (int c = 0; c < 32; c++) {
        if (c < 29) CP_WAIT2(); else CP_WAIT0();
        __syncthreads();
        if (c + 3 < 32) cpB(c + 3);
        if (c + 1 < 32) stsA(c + 1, ra);
        if (c + 2 < 32) ldgA(c + 2, ra);

        const uint32_t aB = base + (uint32_t)(c & 1) * GSTG;
        const uint32_t bB = base + 2 * GSTG + (uint32_t)(c & 3) * GSTG;

#pragma unroll
        for (int s = 0; s < 2; s++) {
            uint32_t a[2][4];
            ldsm4(a[0], aB + (uint32_t)((a_row)*GW + s * 8 + a_wrd) * 4);
            ldsm4(a[1], aB + (uint32_t)((a_row + 16) * GW + s * 8 + a_wrd) * 4);
#pragma unroll
            for (int np = 0; np < 4; np++) {
                uint32_t bb[4];
                ldsm4(bb, bB + (uint32_t)((b_row + np * 16) * GW + s * 8 + b_wrd) * 4);
                mma_f16(acc[0][2 * np],     a[0], bb[0], bb[1]);
                mma_f16(acc[1][2 * np],     a[1], bb[0], bb[1]);
                mma_f16(acc[0][2 * np + 1], a[0], bb[2], bb[3]);
                mma_f16(acc[1][2 * np + 1], a[1], bb[2], bb[3]);
            }
        }
    }

#pragma unroll
    for (int mi = 0; mi < 2; mi++) {
        const int row0 = m0 + wm0 + mi * 16 + lr;
#pragma unroll
        for (int nt = 0; nt < 8; nt++) {
            const int col = wn0 + nt * 8 + 2 * lq;
            __half2 v0 = __float22half2_rn(
                make_float2(acc[mi][nt][0] * scale, acc[mi][nt][1] * scale));
            __half2 v1 = __float22half2_rn(
                make_float2(acc[mi][nt][2] * scale, acc[mi][nt][3] * scale));
            const int gcol = n0 + col;
            const int h = gcol >> 6, d = gcol & 63;
            const int b0i = row0 >> 11, s0 = row0 & 2047;
            *(uint32_t*)&C[(size_t)((b0i * NH + h) * NS + s0) * 64 + d] = *(uint32_t*)&v0;
            const int row1 = row0 + 8;
            const int b1i = row1 >> 11, s1 = row1 & 2047;
            *(uint32_t*)&C[(size_t)((b1i * NH + h) * NS + s1) * 64 + d] = *(uint32_t*)&v1;
        }
    }
}

// ---------------------------------------------------------------------------
// Output projection (R12 exact): 128 threads, warp tile 64x64, 4-stage.
// ---------------------------------------------------------------------------
__global__ __launch_bounds__(128, 2) void gemm_out(const __half* __restrict__ A,
                                                   const __half* __restrict__ BT,
                                                   float* __restrict__ C,
                                                   const float* __restrict__ resid) {
    extern __shared__ __align__(16) uint8_t gsm[];
    const uint32_t base = smem_u32(gsm);

    const int tid  = threadIdx.x;
    const int lane = tid & 31;
    const int wid  = tid >> 5;
    const int lr   = lane >> 2;
    const int lq   = lane & 3;
    const int wm0  = (wid & 1) * 64;
    const int wn0  = (wid >> 1) * 64;
    const int m0   = blockIdx.y * 128;
    const int n0   = blockIdx.x * 128;

    const int a_row = wm0 + (lane & 7) + (lane & 8);
    const int a_wrd = (lane >> 4) << 2;
    const int b_row = wn0 + (lane & 7) + ((lane & 16) >> 1);
    const int b_wrd = (lane & 8) ? 4 : 0;

    const uint8_t* Ag = (const uint8_t*)A + (size_t)m0 * 2048;
    const uint8_t* Bg = (const uint8_t*)BT + (size_t)n0 * 2048;

    auto prefetch = [&](int c) {
        const int stg = c & 3;
        const uint32_t aB = base + (uint32_t)stg * GSTG;
        const uint32_t bB = base + 4 * GSTG + (uint32_t)stg * GSTG;
        const size_t koff = (size_t)c * 64;
#pragma unroll
        for (int i = 0; i < 4; i++) {
            const int idx = tid + 128 * i;
            const int r = idx >> 2, seg = idx & 3;
            const uint32_t so = (uint32_t)(r * GW + seg * 4) * 4;
            cp16(aB + so, Ag + (size_t)r * 2048 + koff + seg * 16);
            cp16(bB + so, Bg + (size_t)r * 2048 + koff + seg * 16);
        }
        CP_COMMIT();
    };

    float acc[4][8][4];
#pragma unroll
    for (int mi = 0; mi < 4; mi++)
#pragma unroll
        for (int nt = 0; nt < 8; nt++)
#pragma unroll
            for (int v = 0; v < 4; v++) acc[mi][nt][v] = 0.f;

    prefetch(0);
    prefetch(1);
    prefetch(2);

    for (int c = 0; c < 32; c++) {
        if (c < 29) CP_WAIT2(); else CP_WAIT0();
        __syncthreads();
        if (c + 3 < 32) prefetch(c + 3);

        const int stg = c & 3;
        const uint32_t aB = base + (uint32_t)stg * GSTG;
        const uint32_t bB = base + 4 * GSTG + (uint32_t)stg * GSTG;

#pragma unroll
        for (int s = 0; s < 2; s++) {
            uint32_t a[4][4];
#pragma unroll
            for (int mi = 0; mi < 4; mi++)
                ldsm4(a[mi], aB + (uint32_t)((a_row + mi * 16) * GW + s * 8 + a_wrd) * 4);
#pragma unroll
            for (int np = 0; np < 4; np++) {
                uint32_t bb[4];
                ldsm4(bb, bB + (uint32_t)((b_row + np * 16) * GW + s * 8 + b_wrd) * 4);
#pragma unroll
                for (int mi = 0; mi < 4; mi++) {
                    mma_f16(acc[mi][2 * np],     a[mi], bb[0], bb[1]);
                    mma_f16(acc[mi][2 * np + 1], a[mi], bb[2], bb[3]);
                }
            }
        }
    }

#pragma unroll
    for (int mi = 0; mi < 4; mi++) {
        const int row0 = m0 + wm0 + mi * 16 + lr;
#pragma unroll
        for (int nt = 0; nt < 8; nt++) {
            const int col = n0 + wn0 + nt * 8 + 2 * lq;
            float2 q0 = *(const float2*)&resid[(size_t)row0 * NDM + col];
            float2 q1 = *(const float2*)&resid[(size_t)(row0 + 8) * NDM + col];
            *(float2*)&C[(size_t)row0 * NDM + col] =
                make_float2(acc[mi][nt][0] + q0.x, acc[mi][nt][1] + q0.y);
            *(float2*)&C[(size_t)(row0 + 8) * NDM + col] =
                make_float2(acc[mi][nt][2] + q1.x, acc[mi][nt][3] + q1.y);
        }
    }
}

// ---------------------------------------------------------------------------
// Flash attention, causal, fp16 mma. R12 base + exact warp-tile skipping:
//  - warps 0-3 skip the fully-masked kt=2qt+1 tile entirely (exact no-op)
//  - mask applied only on each warp's true diagonal tile
//  - rescale skipped when the running max is unchanged (corr==1 exactly)
// ---------------------------------------------------------------------------
#define ST 72
#define ATTN_SMEM_BYTES ((128 + 2 * 64 + 2 * 64) * ST * 2)   // 55296

__global__ __launch_bounds__(256, 2) void attn_h(const __half* __restrict__ Qh,
                                                 const __half* __restrict__ Kh,
                                                 const __half* __restrict__ Vh,
                                                 __half* __restrict__ ctx) {
    extern __shared__ __half smh[];
    __half* Qs = smh;
    __half* Ks0 = Qs + 128 * ST;
    __half* Vs0 = Ks0 + 2 * 64 * ST;
    const uint32_t qsU = smem_u32(Qs);
    const uint32_t ksU = smem_u32(Ks0);
    const uint32_t vsU = smem_u32(Vs0);
    const uint32_t KVSTG = 64 * ST * 2;

    const int tid  = threadIdx.x;
    const int lane = tid & 31;
    const int wid  = tid >> 5;
    const int lr   = lane >> 2;
    const int lq   = lane & 3;

    const int qt = gridDim.x - 1 - blockIdx.x;
    const int bh = blockIdx.y;

    const __half* Qb = Qh + (size_t)bh * NS * 64;
    const __half* Kb = Kh + (size_t)bh * NS * 64;
    const __half* Vb = Vh + (size_t)bh * NS * 64;

    auto prefetch = [&](int kt, int st) {
#pragma unroll
        for (int i = 0; i < 2; i++) {
            const int idx = tid + 256 * i;
            const int r = idx >> 3, cu = idx & 7;
            cp16(ksU + (uint32_t)st * KVSTG + (uint32_t)(r * ST + cu * 8) * 2,
                 Kb + (size_t)(kt * 64 + r) * 64 + cu * 8);
            cp16(vsU + (uint32_t)st * KVSTG + (uint32_t)(r * ST + cu * 8) * 2,
                 Vb + (size_t)(kt * 64 + r) * 64 + cu * 8);
        }
        CP_COMMIT();
    };

    prefetch(0, 0);
#pragma unroll
    for (int i = 0; i < 4; i++) {
        const int idx = tid + 256 * i;
        const int r = idx >> 3, cu = idx & 7;
        *(uint4*)&Qs[r * ST + cu * 8] =
            *(const uint4*)(Qb + (size_t)(qt * 128 + r) * 64 + cu * 8);
    }
    __syncthreads();

    uint32_t qf[4][4];
    {
        const int arow = wid * 16 + (lane & 7) + (lane & 8);
        const int acol = (lane & 16) >> 1;
#pragma unroll
        for (int s = 0; s < 4; s++)
            ldsm4(qf[s], qsU + (uint32_t)(arow * ST + s * 16 + acol) * 2);
    }

    float o[8][4];
#pragma unroll
    for (int nt = 0; nt < 8; nt++)
#pragma unroll
        for (int v = 0; v < 4; v++) o[nt][v] = 0.f;
    float osum[4] = {0.f, 0.f, 0.f, 0.f};
    float mrow0 = -1e30f, mrow1 = -1e30f;

    const int qrow0 = qt * 128 + wid * 16 + lr;
    const int qrow1 = qrow0 + 8;
    const int ktmax = 2 * qt + 1;
    const int diagkt = 2 * qt + (wid >> 2);   // the one tile this warp must mask
    const bool lowwarp = (wid < 4);           // rows 0-63: kt=2qt+1 fully masked

    const int kb_row = (lane & 7) + ((lane & 16) >> 1);
    const int kb_col = (lane & 8) ? 8 : 0;
    const int vb_row = (lane & 7) + (lane & 8);
    const int vb_col = (lane & 16) >> 1;

    for (int kt = 0; kt <= ktmax; kt++) {
        const int st = kt & 1;
        CP_WAIT0();
        __syncthreads();
        if (kt < ktmax) prefetch(kt + 1, st ^ 1);

        // fully-masked tile for this warp: exact no-op, skip all compute
        if (lowwarp && kt == ktmax) continue;

        const uint32_t kBase = ksU + (uint32_t)st * KVSTG;
        const uint32_t vBase = vsU + (uint32_t)st * KVSTG;

        float s[8][4];
#pragma unroll
        for (int nt = 0; nt < 8; nt++)
#pragma unroll
            for (int v = 0; v < 4; v++) s[nt][v] = 0.f;

#pragma unroll
        for (int step = 0; step < 4; step++) {
#pragma unroll
            for (int np = 0; np < 4; np++) {
                uint32_t bb[4];
                ldsm4(bb, kBase + (uint32_t)((np * 16 + kb_row) * ST + step * 16 + kb_col) * 2);
                mma_f16(s[2 * np],     qf[step], bb[0], bb[1]);
                mma_f16(s[2 * np + 1], qf[step], bb[2], bb[3]);
            }
        }

        if (kt == diagkt) {
#pragma unroll
            for (int nt = 0; nt < 8; nt++) {
                const int col = kt * 64 + nt * 8 + 2 * lq;
                if (col     > qrow0) s[nt][0] = -1e30f;
                if (col + 1 > qrow0) s[nt][1] = -1e30f;
                if (col     > qrow1) s[nt][2] = -1e30f;
                if (col + 1 > qrow1) s[nt][3] = -1e30f;
            }
        }

        float mx0 = -1e30f, mx1 = -1e30f;
#pragma unroll
        for (int nt = 0; nt < 8; nt++) {
            mx0 = fmaxf(mx0, fmaxf(s[nt][0], s[nt][1]));
            mx1 = fmaxf(mx1, fmaxf(s[nt][2], s[nt][3]));
        }
        __half2 mxh = __float22half2_rn(make_float2(mx0, mx1));
#pragma unroll
        for (int off = 1; off < 4; off <<= 1) {
            uint32_t mu = *(uint32_t*)&mxh;
            uint32_t ou = __shfl_xor_sync(0xffffffffu, mu, off);
            mxh = __hmax2(mxh, *(__half2*)&ou);
        }
        float2 mxf = __half22float2(mxh);
        const float mn0 = fmaxf(mrow0, mxf.x);
        const float mn1 = fmaxf(mrow1, mxf.y);

        // rescale only when the running max actually moved (corr==1 otherwise)
        if (__any_sync(0xffffffffu, (mn0 != mrow0) | (mn1 != mrow1))) {
            const float corr0 = ex2(mrow0 - mn0);
            const float corr1 = ex2(mrow1 - mn1);
#pragma unroll
            for (int nt = 0; nt < 8; nt++) {
                o[nt][0] *= corr0;
                o[nt][1] *= corr0;
                o[nt][2] *= corr1;
                o[nt][3] *= corr1;
            }
            osum[0] *= corr0;
            osum[1] *= corr0;
            osum[2] *= corr1;
            osum[3] *= corr1;
            mrow0 = mn0;
            mrow1 = mn1;
        }

        uint32_t pf[4][4];
#pragma unroll
        for (int s4 = 0; s4 < 4; s4++) {
            pf[s4][0] = ex2h2(s[2 * s4][0] - mrow0,     s[2 * s4][1] - mrow0);
            pf[s4][1] = ex2h2(s[2 * s4][2] - mrow1,     s[2 * s4][3] - mrow1);
            pf[s4][2] = ex2h2(s[2 * s4 + 1][0] - mrow0, s[2 * s4 + 1][1] - mrow0);
            pf[s4][3] = ex2h2(s[2 * s4 + 1][2] - mrow1, s[2 * s4 + 1][3] - mrow1);
        }

#pragma unroll
        for (int step = 0; step < 4; step++) {
#pragma unroll
            for (int np = 0; np < 4; np++) {
                uint32_t bb[4];
                ldsm4t(bb, vBase + (uint32_t)((step * 16 + vb_row) * ST + np * 16 + vb_col) * 2);
                mma_f16(o[2 * np],     pf[step], bb[0], bb[1]);
                mma_f16(o[2 * np + 1], pf[step], bb[2], bb[3]);
            }
            mma_f16(osum, pf[step], ONES_H2, ONES_H2);
        }
    }

    const int b = bh >> 4;
    const int h = bh & 15;
    const float inv0 = 1.f / osum[0];
    const float inv1 = 1.f / osum[2];
    const int srow = qt * 128 + wid * 16 + lr;
#pragma unroll
    for (int nt = 0; nt < 8; nt++) {
        const int d = nt * 8 + 2 * lq;
        __half2 p0 = __float22half2_rn(make_float2(o[nt][0] * inv0, o[nt][1] * inv0));
        __half2 p1 = __float22half2_rn(make_float2(o[nt][2] * inv1, o[nt][3] * inv1));
        *(uint32_t*)&ctx[(size_t)(b * NS + srow) * NDM + h * 64 + d] = *(uint32_t*)&p0;
        *(uint32_t*)&ctx[(size_t)(b * NS + srow + 8) * NDM + h * 64 + d] = *(uint32_t*)&p1;
    }
}

// ---------------------------------------------------------------------------
// LayerNorm (residual already folded in by gemm_out), in-place on out.
// ---------------------------------------------------------------------------
__global__ __launch_bounds__(256) void ln_kernel(const float* __restrict__ gamma,
                                                 const float* __restrict__ beta,
                                                 float* __restrict__ out) {
    __shared__ float rs[8], rq[8], fin[2];
    const int row = blockIdx.x;
    const int tid = threadIdx.x;
    const int c   = tid << 2;

    float4 x4 = *(const float4*)(out + (size_t)row * NDM + c);
    const float x0 = x4.x, x1 = x4.y, x2 = x4.z, x3 = x4.w;
    float s  = x0 + x1 + x2 + x3;
    float sq = x0 * x0 + x1 * x1 + x2 * x2 + x3 * x3;
#pragma unroll
    for (int off = 16; off; off >>= 1) {
        s  += __shfl_xor_sync(0xffffffffu, s, off);
        sq += __shfl_xor_sync(0xffffffffu, sq, off);
    }
    const int wid = tid >> 5, lane = tid & 31;
    if (lane == 0) { rs[wid] = s; rq[wid] = sq; }
    __syncthreads();
    if (tid == 0) {
        float a = 0.f, b2 = 0.f;
#pragma unroll
        for (int i = 0; i < 8; i++) { a += rs[i]; b2 += rq[i]; }
        fin[0] = a;
        fin[1] = b2;
    }
    __syncthreads();
    const float mu   = fin[0] * (1.0f / NDM);
    const float var  = fin[1] * (1.0f / NDM) - mu * mu;
    const float rstd = rsqrtf(var + 1e-5f);

    float4 g4 = *(const float4*)(gamma + c);
    float4 b4 = *(const float4*)(beta + c);
    float4 r;
    r.x = (x0 - mu) * rstd * g4.x + b4.x;
    r.y = (x1 - mu) * rstd * g4.y + b4.y;
    r.z = (x2 - mu) * rstd * g4.z + b4.z;
    r.w = (x3 - mu) * rstd * g4.w + b4.w;
    *(float4*)(out + (size_t)row * NDM + c) = r;
}

// ---------------------------------------------------------------------------
// Launch
// ---------------------------------------------------------------------------
extern "C" void kernel_launch(void* const* d_in, const int* in_sizes, int n_in,
                              void* d_out, int out_size) {
    const float* Q     = (const float*)d_in[0];
    const float* K     = (const float*)d_in[1];
    const float* V     = (const float*)d_in[2];
    const float* W_Q   = (const float*)d_in[3];
    const float* W_K   = (const float*)d_in[4];
    const float* W_V   = (const float*)d_in[5];
    const float* W_O   = (const float*)d_in[6];
    const float* gamma = (const float*)d_in[7];
    const float* beta  = (const float*)d_in[8];
    float* out = (float*)d_out;

    __half *qh, *kh, *vh, *ctxh, *wtq, *wtk, *wtv, *wto;
    cudaGetSymbolAddress((void**)&qh,   g_Qh);
    cudaGetSymbolAddress((void**)&kh,   g_Kh);
    cudaGetSymbolAddress((void**)&vh,   g_Vh);
    cudaGetSymbolAddress((void**)&ctxh, g_ctxh);
    cudaGetSymbolAddress((void**)&wtq,  g_WTq);
    cudaGetSymbolAddress((void**)&wtk,  g_WTk);
    cudaGetSymbolAddress((void**)&wtv,  g_WTv);
    cudaGetSymbolAddress((void**)&wto,  g_WTo);

    cudaFuncSetAttribute(attn_h, cudaFuncAttributeMaxDynamicSharedMemorySize,
                         ATTN_SMEM_BYTES);
    cudaFuncSetAttribute(gemm_qkv, cudaFuncAttributeMaxDynamicSharedMemorySize,
                         QKV_SMEM);
    cudaFuncSetAttribute(gemm_out, cudaFuncAttributeMaxDynamicSharedMemorySize,
                         OUT_SMEM);

    // weight transposes (fp32 -> fp16 W^T)
    wtrans4_kernel<<<dim3(32, 32, 4), 256>>>(W_Q, W_K, W_V, W_O, wtq, wtk, wtv, wto);

    // QKV projections straight from fp32 inputs (Q pre-scaled by 0.125*log2e)
    gemm_qkv<<<dim3(NDM / 128, NM / 128, 3), 256, QKV_SMEM>>>(
        Q, K, V, wtq, wtk, wtv, qh, kh, vh);

    // attention (fp16, register P, MMA row-sums), writes fp16 ctx
    attn_h<<<dim3(NS / 128, NB * NH), 256, ATTN_SMEM_BYTES>>>(qh, kh, vh, ctxh);

    // output projection + fused residual, then LN
    gemm_out<<<dim3(NDM / 128, NM / 128), 128, OUT_SMEM>>>(ctxh, wto, out, Q);
    ln_kernel<<<NM, 256>>>(gamma, beta, out);
}

// round 16
// speedup vs baseline: 1.0415x; 1.0295x over previous
#include <cuda_runtime.h>
#include <cuda_fp16.h>
#include <cstdint>

// Problem constants
#define NB   4
#define NS   2048
#define NDM  1024
#define NH   16
#define NM   (NB * NS)      // 8192 rows

// ---------------------------------------------------------------------------
// Device scratch
// ---------------------------------------------------------------------------
__device__ __half g_Qh[NB * NH * NS * 64];   // fp16 heads [B,H,S,64] (Q pre-scaled)
__device__ __half g_Kh[NB * NH * NS * 64];
__device__ __half g_Vh[NB * NH * NS * 64];
__device__ __half g_ctxh[NM * NDM];          // fp16 ctx [B*S, H*Dv]

__device__ __half g_WTq[NDM * NDM];          // fp16 W^T [n][k]
__device__ __half g_WTk[NDM * NDM];
__device__ __half g_WTv[NDM * NDM];
__device__ __half g_WTo[NDM * NDM];

// scale folded into Q heads: 1/sqrt(64) * log2(e)
#define QSCALE 0.18033688011112042f
#define ONES_H2 0x3C003C00u      // half2(1.0, 1.0)

// ---------------------------------------------------------------------------
// mma / ldmatrix / cp.async helpers
// ---------------------------------------------------------------------------
__device__ __forceinline__ uint32_t smem_u32(const void* p) {
    uint32_t a;
    asm("{ .reg .u64 t; cvta.to.shared.u64 t, %1; cvt.u32.u64 %0, t; }"
        : "=r"(a) : "l"(p));
    return a;
}

__device__ __forceinline__ void ldsm4(uint32_t r[4], uint32_t addr) {
    asm volatile("ldmatrix.sync.aligned.m8n8.x4.shared.b16 {%0,%1,%2,%3}, [%4];"
                 : "=r"(r[0]), "=r"(r[1]), "=r"(r[2]), "=r"(r[3]) : "r"(addr));
}

__device__ __forceinline__ void ldsm4t(uint32_t r[4], uint32_t addr) {
    asm volatile("ldmatrix.sync.aligned.m8n8.x4.trans.shared.b16 {%0,%1,%2,%3}, [%4];"
                 : "=r"(r[0]), "=r"(r[1]), "=r"(r[2]), "=r"(r[3]) : "r"(addr));
}

__device__ __forceinline__ void mma_f16(float c[4], const uint32_t a[4],
                                        uint32_t b0, uint32_t b1) {
    asm volatile(
        "mma.sync.aligned.m16n8k16.row.col.f32.f16.f16.f32 "
        "{%0,%1,%2,%3}, {%4,%5,%6,%7}, {%8,%9}, {%0,%1,%2,%3};"
        : "+f"(c[0]), "+f"(c[1]), "+f"(c[2]), "+f"(c[3])
        : "r"(a[0]), "r"(a[1]), "r"(a[2]), "r"(a[3]), "r"(b0), "r"(b1));
}

__device__ __forceinline__ void cp16(uint32_t dst, const void* src) {
    asm volatile("cp.async.cg.shared.global [%0], [%1], 16;" :: "r"(dst), "l"(src));
}
#define CP_COMMIT() asm volatile("cp.async.commit_group;")
#define CP_WAIT0()  asm volatile("cp.async.wait_group 0;")
#define CP_WAIT2()  asm volatile("cp.async.wait_group 2;")

__device__ __forceinline__ float ex2(float x) {
    float r;
    asm("ex2.approx.f32 %0, %1;" : "=f"(r) : "f"(x));
    return r;
}

__device__ __forceinline__ uint32_t ex2h2(float a, float b) {
    __half2 h = __float22half2_rn(make_float2(a, b));
    uint32_t u = *(uint32_t*)&h;
    asm("ex2.approx.f16x2 %0, %0;" : "+r"(u));
    return u;
}

// ---------------------------------------------------------------------------
// Weight transpose: W [k][n] fp32 -> WT [n][k] fp16, batched over z
// ---------------------------------------------------------------------------
__global__ __launch_bounds__(256) void wtrans4_kernel(const float* __restrict__ w0,
                                                      const float* __restrict__ w1,
                                                      const float* __restrict__ w2,
                                                      const float* __restrict__ w3,
                                                      __half* t0, __half* t1,
                                                      __half* t2, __half* t3) {
    __shared__ float t[32][33];
    const int z = blockIdx.z;
    const float* W = (z == 0) ? w0 : (z == 1) ? w1 : (z == 2) ? w2 : w3;
    __half* WT = (z == 0) ? t0 : (z == 1) ? t1 : (z == 2) ? t2 : t3;
    const int tx = threadIdx.x & 31;
    const int ty = threadIdx.x >> 5;
    const int bn = blockIdx.x * 32;
    const int bk = blockIdx.y * 32;
#pragma unroll
    for (int i = 0; i < 4; i++)
        t[ty + 8 * i][tx] = W[(size_t)(bk + ty + 8 * i) * NDM + bn + tx];
    __syncthreads();
#pragma unroll
    for (int i = 0; i < 4; i++)
        WT[(size_t)(bn + ty + 8 * i) * NDM + bk + tx] =
            __float2half(t[tx][ty + 8 * i]);
}

// ---------------------------------------------------------------------------
// Shared GEMM constants (R12 exact)
// ---------------------------------------------------------------------------
#define GW 20                        // 32-bit words per smem row
#define GSTG 10240                   // bytes per BK=32 stage (128 rows)
#define QKV_SMEM (2 * GSTG + 4 * GSTG)   // 61440
#define OUT_SMEM (4 * GSTG + 4 * GSTG)   // 81920

// ---------------------------------------------------------------------------
// QKV projection (R12 exact): 256 threads, warp tile 32x64.
// ---------------------------------------------------------------------------
__global__ __launch_bounds__(256, 2) void gemm_qkv(const float* __restrict__ Qf,
                                                   const float* __restrict__ Kf,
                                                   const float* __restrict__ Vf,
                                                   const __half* __restrict__ wtq,
                                                   const __half* __restrict__ wtk,
                                                   const __half* __restrict__ wtv,
                                                   __half* qh, __half* kh, __half* vh) {
    extern __shared__ __align__(16) uint8_t gsm[];
    const uint32_t base = smem_u32(gsm);

    const int z = blockIdx.z;
    const float* A   = (z == 0) ? Qf : (z == 1) ? Kf : Vf;
    const __half* BT = (z == 0) ? wtq : (z == 1) ? wtk : wtv;
    __half* C        = (z == 0) ? qh : (z == 1) ? kh : vh;
    const float scale = (z == 0) ? QSCALE : 1.0f;

    const int tid  = threadIdx.x;
    const int lane = tid & 31;
    const int wid  = tid >> 5;
    const int lr   = lane >> 2;
    const int lq   = lane & 3;
    const int wm0  = (wid & 3) * 32;
    const int wn0  = (wid >> 2) * 64;
    const int m0   = blockIdx.y * 128;
    const int n0   = blockIdx.x * 128;

    const int a_row = wm0 + (lane & 7) + (lane & 8);
    const int a_wrd = (lane >> 4) << 2;
    const int b_row = wn0 + (lane & 7) + ((lane & 16) >> 1);
    const int b_wrd = (lane & 8) ? 4 : 0;

    const int br = tid >> 2;
    const int bc = tid & 3;
    const uint8_t* Bg = (const uint8_t*)BT + (size_t)n0 * 2048 + bc * 16;

    auto cpB = [&](int c) {
        const uint32_t bB = base + 2 * GSTG + (uint32_t)(c & 3) * GSTG;
        const size_t koff = (size_t)c * 64;
#pragma unroll
        for (int i = 0; i < 2; i++) {
            const uint32_t so = (uint32_t)((br + 64 * i) * GW + bc * 4) * 4;
            cp16(bB + so, Bg + (size_t)(br + 64 * i) * 2048 + koff);
        }
        CP_COMMIT();
    };

    auto ldgA = [&](int c, float4 ra[4]) {
#pragma unroll
        for (int i = 0; i < 4; i++) {
            const int gidx = tid + 256 * i;
            const int r = gidx >> 3, seg = gidx & 7;
            ra[i] = *(const float4*)(A + (size_t)(m0 + r) * NDM + c * 32 + seg * 4);
        }
    };
    auto stsA = [&](int c, const float4 ra[4]) {
        const uint32_t off = (uint32_t)(c & 1) * GSTG;
#pragma unroll
        for (int i = 0; i < 4; i++) {
            const int gidx = tid + 256 * i;
            const int r = gidx >> 3, seg = gidx & 7;
            __half2 h0 = __float22half2_rn(make_float2(ra[i].x, ra[i].y));
            __half2 h1 = __float22half2_rn(make_float2(ra[i].z, ra[i].w));
            uint2 u = make_uint2(*(uint32_t*)&h0, *(uint32_t*)&h1);
            *(uint2*)(gsm + off + (uint32_t)(r * GW + seg * 2) * 4) = u;
        }
    };

    float acc[2][8][4];
#pragma unroll
    for (int mi = 0; mi < 2; mi++)
#pragma unroll
        for (int nt = 0; nt < 8; nt++)
#pragma unroll
            for (int v = 0; v < 4; v++) acc[mi][nt][v] = 0.f;

    float4 ra[4];
    ldgA(0, ra);
    cpB(0); cpB(1); cpB(2);
    stsA(0, ra);
    ldgA(1, ra);

    for (int c = 0; c < 32; c++) {
        if (c < 29) CP_WAIT2(); else CP_WAIT0();
        __syncthreads();
        if (c + 3 < 32) cpB(c + 3);
        if (c + 1 < 32) stsA(c + 1, ra);
        if (c + 2 < 32) ldgA(c + 2, ra);

        const uint32_t aB = base + (uint32_t)(c & 1) * GSTG;
        const uint32_t bB = base + 2 * GSTG + (uint32_t)(c & 3) * GSTG;

#pragma unroll
        for (int s = 0; s < 2; s++) {
            uint32_t a[2][4];
            ldsm4(a[0], aB + (uint32_t)((a_row)*GW + s * 8 + a_wrd) * 4);
            ldsm4(a[1], aB + (uint32_t)((a_row + 16) * GW + s * 8 + a_wrd) * 4);
#pragma unroll
            for (int np = 0; np < 4; np++) {
                uint32_t bb[4];
                ldsm4(bb, bB + (uint32_t)((b_row + np * 16) * GW + s * 8 + b_wrd) * 4);
                mma_f16(acc[0][2 * np],     a[0], bb[0], bb[1]);
                mma_f16(acc[1][2 * np],     a[1], bb[0], bb[1]);
                mma_f16(acc[0][2 * np + 1], a[0], bb[2], bb[3]);
                mma_f16(acc[1][2 * np + 1], a[1], bb[2], bb[3]);
            }
        }
    }

#pragma unroll
    for (int mi = 0; mi < 2; mi++) {
        const int row0 = m0 + wm0 + mi * 16 + lr;
#pragma unroll
        for (int nt = 0; nt < 8; nt++) {
            const int col = wn0 + nt * 8 + 2 * lq;
            __half2 v0 = __float22half2_rn(
                make_float2(acc[mi][nt][0] * scale, acc[mi][nt][1] * scale));
            __half2 v1 = __float22half2_rn(
                make_float2(acc[mi][nt][2] * scale, acc[mi][nt][3] * scale));
            const int gcol = n0 + col;
            const int h = gcol >> 6, d = gcol & 63;
            const int b0i = row0 >> 11, s0 = row0 & 2047;
            *(uint32_t*)&C[(size_t)((b0i * NH + h) * NS + s0) * 64 + d] = *(uint32_t*)&v0;
            const int row1 = row0 + 8;
            const int b1i = row1 >> 11, s1 = row1 & 2047;
            *(uint32_t*)&C[(size_t)((b1i * NH + h) * NS + s1) * 64 + d] = *(uint32_t*)&v1;
        }
    }
}

// ---------------------------------------------------------------------------
// Output projection (R12 exact): 128 threads, warp tile 64x64, 4-stage.
// ---------------------------------------------------------------------------
__global__ __launch_bounds__(128, 2) void gemm_out(const __half* __restrict__ A,
                                                   const __half* __restrict__ BT,
                                                   float* __restrict__ C,
                                                   const float* __restrict__ resid) {
    extern __shared__ __align__(16) uint8_t gsm[];
    const uint32_t base = smem_u32(gsm);

    const int tid  = threadIdx.x;
    const int lane = tid & 31;
    const int wid  = tid >> 5;
    const int lr   = lane >> 2;
    const int lq   = lane & 3;
    const int wm0  = (wid & 1) * 64;
    const int wn0  = (wid >> 1) * 64;
    const int m0   = blockIdx.y * 128;
    const int n0   = blockIdx.x * 128;

    const int a_row = wm0 + (lane & 7) + (lane & 8);
    const int a_wrd = (lane >> 4) << 2;
    const int b_row = wn0 + (lane & 7) + ((lane & 16) >> 1);
    const int b_wrd = (lane & 8) ? 4 : 0;

    const uint8_t* Ag = (const uint8_t*)A + (size_t)m0 * 2048;
    const uint8_t* Bg = (const uint8_t*)BT + (size_t)n0 * 2048;

    auto prefetch = [&](int c) {
        const int stg = c & 3;
        const uint32_t aB = base + (uint32_t)stg * GSTG;
        const uint32_t bB = base + 4 * GSTG + (uint32_t)stg * GSTG;
        const size_t koff = (size_t)c * 64;
#pragma unroll
        for (int i = 0; i < 4; i++) {
            const int idx = tid + 128 * i;
            const int r = idx >> 2, seg = idx & 3;
            const uint32_t so = (uint32_t)(r * GW + seg * 4) * 4;
            cp16(aB + so, Ag + (size_t)r * 2048 + koff + seg * 16);
            cp16(bB + so, Bg + (size_t)r * 2048 + koff + seg * 16);
        }
        CP_COMMIT();
    };

    float acc[4][8][4];
#pragma unroll
    for (int mi = 0; mi < 4; mi++)
#pragma unroll
        for (int nt = 0; nt < 8; nt++)
#pragma unroll
            for (int v = 0; v < 4; v++) acc[mi][nt][v] = 0.f;

    prefetch(0);
    prefetch(1);
    prefetch(2);

    for (int c = 0; c < 32; c++) {
        if (c < 29) CP_WAIT2(); else CP_WAIT0();
        __syncthreads();
        if (c + 3 < 32) prefetch(c + 3);

        const int stg = c & 3;
        const uint32_t aB = base + (uint32_t)stg * GSTG;
        const uint32_t bB = base + 4 * GSTG + (uint32_t)stg * GSTG;

#pragma unroll
        for (int s = 0; s < 2; s++) {
            uint32_t a[4][4];
#pragma unroll
            for (int mi = 0; mi < 4; mi++)
                ldsm4(a[mi], aB + (uint32_t)((a_row + mi * 16) * GW + s * 8 + a_wrd) * 4);
#pragma unroll
            for (int np = 0; np < 4; np++) {
                uint32_t bb[4];
                ldsm4(bb, bB + (uint32_t)((b_row + np * 16) * GW + s * 8 + b_wrd) * 4);
#pragma unroll
                for (int mi = 0; mi < 4; mi++) {
                    mma_f16(acc[mi][2 * np],     a[mi], bb[0], bb[1]);
                    mma_f16(acc[mi][2 * np + 1], a[mi], bb[2], bb[3]);
                }
            }
        }
    }

#pragma unroll
    for (int mi = 0; mi < 4; mi++) {
        const int row0 = m0 + wm0 + mi * 16 + lr;
#pragma unroll
        for (int nt = 0; nt < 8; nt++) {
            const int col = n0 + wn0 + nt * 8 + 2 * lq;
            float2 q0 = *(const float2*)&resid[(size_t)row0 * NDM + col];
            float2 q1 = *(const float2*)&resid[(size_t)(row0 + 8) * NDM + col];
            *(float2*)&C[(size_t)row0 * NDM + col] =
                make_float2(acc[mi][nt][0] + q0.x, acc[mi][nt][1] + q0.y);
            *(float2*)&C[(size_t)(row0 + 8) * NDM + col] =
                make_float2(acc[mi][nt][2] + q1.x, acc[mi][nt][3] + q1.y);
        }
    }
}

// ---------------------------------------------------------------------------
// Flash attention, causal, fp16 mma. 4 warps (128 thr), warp Q-tile 32 rows
// (two m16 blocks per warp) -> each K/V fragment feeds 4 MMAs (was 2),
// halving smem LDSM traffic. 2-stage K/V cp.async ring (R12 pipeline).
// ---------------------------------------------------------------------------
#define ST 72
#define ATTN_SMEM_BYTES ((128 + 2 * 64 + 2 * 64) * ST * 2)   // 55296

__global__ __launch_bounds__(128, 2) void attn_h(const __half* __restrict__ Qh,
                                                 const __half* __restrict__ Kh,
                                                 const __half* __restrict__ Vh,
                                                 __half* __restrict__ ctx) {
    extern __shared__ __half smh[];
    __half* Qs = smh;
    __half* Ks0 = Qs + 128 * ST;
    __half* Vs0 = Ks0 + 2 * 64 * ST;
    const uint32_t qsU = smem_u32(Qs);
    const uint32_t ksU = smem_u32(Ks0);
    const uint32_t vsU = smem_u32(Vs0);
    const uint32_t KVSTG = 64 * ST * 2;

    const int tid  = threadIdx.x;
    const int lane = tid & 31;
    const int wid  = tid >> 5;          // 0..3
    const int lr   = lane >> 2;
    const int lq   = lane & 3;

    const int qt = gridDim.x - 1 - blockIdx.x;
    const int bh = blockIdx.y;

    const __half* Qb = Qh + (size_t)bh * NS * 64;
    const __half* Kb = Kh + (size_t)bh * NS * 64;
    const __half* Vb = Vh + (size_t)bh * NS * 64;

    auto prefetch = [&](int kt, int st) {
#pragma unroll
        for (int i = 0; i < 4; i++) {
            const int idx = tid + 128 * i;
            const int r = idx >> 3, cu = idx & 7;
            cp16(ksU + (uint32_t)st * KVSTG + (uint32_t)(r * ST + cu * 8) * 2,
                 Kb + (size_t)(kt * 64 + r) * 64 + cu * 8);
            cp16(vsU + (uint32_t)st * KVSTG + (uint32_t)(r * ST + cu * 8) * 2,
                 Vb + (size_t)(kt * 64 + r) * 64 + cu * 8);
        }
        CP_COMMIT();
    };

    prefetch(0, 0);
#pragma unroll
    for (int i = 0; i < 8; i++) {
        const int idx = tid + 128 * i;
        const int r = idx >> 3, cu = idx & 7;
        *(uint4*)&Qs[r * ST + cu * 8] =
            *(const uint4*)(Qb + (size_t)(qt * 128 + r) * 64 + cu * 8);
    }
    __syncthreads();

    // Hoist Q fragments: warp owns rows [32*wid, 32*wid+32) = 2 m16 blocks.
    uint32_t qf[2][4][4];
    {
        const int alr = (lane & 7) + (lane & 8);
        const int acol = (lane & 16) >> 1;
#pragma unroll
        for (int mi = 0; mi < 2; mi++)
#pragma unroll
            for (int s = 0; s < 4; s++)
                ldsm4(qf[mi][s],
                      qsU + (uint32_t)((wid * 32 + mi * 16 + alr) * ST + s * 16 + acol) * 2);
    }

    float o[2][8][4];
#pragma unroll
    for (int mi = 0; mi < 2; mi++)
#pragma unroll
        for (int nt = 0; nt < 8; nt++)
#pragma unroll
            for (int v = 0; v < 4; v++) o[mi][nt][v] = 0.f;
    float osum[2][4] = {{0.f, 0.f, 0.f, 0.f}, {0.f, 0.f, 0.f, 0.f}};
    float mrow0[2] = {-1e30f, -1e30f};
    float mrow1[2] = {-1e30f, -1e30f};

    const int ktmax = 2 * qt + 1;

    const int kb_row = (lane & 7) + ((lane & 16) >> 1);
    const int kb_col = (lane & 8) ? 8 : 0;
    const int vb_row = (lane & 7) + (lane & 8);
    const int vb_col = (lane & 16) >> 1;

    for (int kt = 0; kt <= ktmax; kt++) {
        const int st = kt & 1;
        CP_WAIT0();
        __syncthreads();
        if (kt < ktmax) prefetch(kt + 1, st ^ 1);

        const uint32_t kBase = ksU + (uint32_t)st * KVSTG;
        const uint32_t vBase = vsU + (uint32_t)st * KVSTG;

        // ---- S = Q K^T: K fragment shared across both m-blocks ----
        float s[2][8][4];
#pragma unroll
        for (int mi = 0; mi < 2; mi++)
#pragma unroll
            for (int nt = 0; nt < 8; nt++)
#pragma unroll
                for (int v = 0; v < 4; v++) s[mi][nt][v] = 0.f;

#pragma unroll
        for (int step = 0; step < 4; step++) {
#pragma unroll
            for (int np = 0; np < 4; np++) {
                uint32_t bb[4];
                ldsm4(bb, kBase + (uint32_t)((np * 16 + kb_row) * ST + step * 16 + kb_col) * 2);
                mma_f16(s[0][2 * np],     qf[0][step], bb[0], bb[1]);
                mma_f16(s[0][2 * np + 1], qf[0][step], bb[2], bb[3]);
                mma_f16(s[1][2 * np],     qf[1][step], bb[0], bb[1]);
                mma_f16(s[1][2 * np + 1], qf[1][step], bb[2], bb[3]);
            }
        }

        // causal mask (diagonal region)
        if (kt >= 2 * qt) {
#pragma unroll
            for (int mi = 0; mi < 2; mi++) {
                const int qrow0 = qt * 128 + wid * 32 + mi * 16 + lr;
                const int qrow1 = qrow0 + 8;
#pragma unroll
                for (int nt = 0; nt < 8; nt++) {
                    const int col = kt * 64 + nt * 8 + 2 * lq;
                    if (col     > qrow0) s[mi][nt][0] = -1e30f;
                    if (col + 1 > qrow0) s[mi][nt][1] = -1e30f;
                    if (col     > qrow1) s[mi][nt][2] = -1e30f;
                    if (col + 1 > qrow1) s[mi][nt][3] = -1e30f;
                }
            }
        }

        // ---- online softmax + PV per m-block ----
        uint32_t pf[2][4][4];
#pragma unroll
        for (int mi = 0; mi < 2; mi++) {
            float mx0 = -1e30f, mx1 = -1e30f;
#pragma unroll
            for (int nt = 0; nt < 8; nt++) {
                mx0 = fmaxf(mx0, fmaxf(s[mi][nt][0], s[mi][nt][1]));
                mx1 = fmaxf(mx1, fmaxf(s[mi][nt][2], s[mi][nt][3]));
            }
            __half2 mxh = __float22half2_rn(make_float2(mx0, mx1));
#pragma unroll
            for (int off = 1; off < 4; off <<= 1) {
                uint32_t mu = *(uint32_t*)&mxh;
                uint32_t ou = __shfl_xor_sync(0xffffffffu, mu, off);
                mxh = __hmax2(mxh, *(__half2*)&ou);
            }
            float2 mxf = __half22float2(mxh);
            const float mn0 = fmaxf(mrow0[mi], mxf.x);
            const float mn1 = fmaxf(mrow1[mi], mxf.y);
            const float corr0 = ex2(mrow0[mi] - mn0);
            const float corr1 = ex2(mrow1[mi] - mn1);
            mrow0[mi] = mn0;
            mrow1[mi] = mn1;

#pragma unroll
            for (int s4 = 0; s4 < 4; s4++) {
                pf[mi][s4][0] = ex2h2(s[mi][2 * s4][0] - mn0,     s[mi][2 * s4][1] - mn0);
                pf[mi][s4][1] = ex2h2(s[mi][2 * s4][2] - mn1,     s[mi][2 * s4][3] - mn1);
                pf[mi][s4][2] = ex2h2(s[mi][2 * s4 + 1][0] - mn0, s[mi][2 * s4 + 1][1] - mn0);
                pf[mi][s4][3] = ex2h2(s[mi][2 * s4 + 1][2] - mn1, s[mi][2 * s4 + 1][3] - mn1);
            }

#pragma unroll
            for (int nt = 0; nt < 8; nt++) {
                o[mi][nt][0] *= corr0;
                o[mi][nt][1] *= corr0;
                o[mi][nt][2] *= corr1;
                o[mi][nt][3] *= corr1;
            }
            osum[mi][0] *= corr0;
            osum[mi][1] *= corr0;
            osum[mi][2] *= corr1;
            osum[mi][3] *= corr1;
        }

        // ---- O += P V: V fragment shared across both m-blocks ----
#pragma unroll
        for (int step = 0; step < 4; step++) {
#pragma unroll
            for (int np = 0; np < 4; np++) {
                uint32_t bb[4];
                ldsm4t(bb, vBase + (uint32_t)((step * 16 + vb_row) * ST + np * 16 + vb_col) * 2);
                mma_f16(o[0][2 * np],     pf[0][step], bb[0], bb[1]);
                mma_f16(o[0][2 * np + 1], pf[0][step], bb[2], bb[3]);
                mma_f16(o[1][2 * np],     pf[1][step], bb[0], bb[1]);
                mma_f16(o[1][2 * np + 1], pf[1][step], bb[2], bb[3]);
            }
            mma_f16(osum[0], pf[0][step], ONES_H2, ONES_H2);
            mma_f16(osum[1], pf[1][step], ONES_H2, ONES_H2);
        }
    }

    // write ctx as fp16 [B*S, H*64]
    const int b = bh >> 4;
    const int h = bh & 15;
#pragma unroll
    for (int mi = 0; mi < 2; mi++) {
        const float inv0 = 1.f / osum[mi][0];
        const float inv1 = 1.f / osum[mi][2];
        const int srow = qt * 128 + wid * 32 + mi * 16 + lr;
#pragma unroll
        for (int nt = 0; nt < 8; nt++) {
            const int d = nt * 8 + 2 * lq;
            __half2 p0 = __float22half2_rn(make_float2(o[mi][nt][0] * inv0, o[mi][nt][1] * inv0));
            __half2 p1 = __float22half2_rn(make_float2(o[mi][nt][2] * inv1, o[mi][nt][3] * inv1));
            *(uint32_t*)&ctx[(size_t)(b * NS + srow) * NDM + h * 64 + d] = *(uint32_t*)&p0;
            *(uint32_t*)&ctx[(size_t)(b * NS + srow + 8) * NDM + h * 64 + d] = *(uint32_t*)&p1;
        }
    }
}

// ---------------------------------------------------------------------------
// LayerNorm (residual already folded in by gemm_out), in-place on out.
// ---------------------------------------------------------------------------
__global__ __launch_bounds__(256) void ln_kernel(const float* __restrict__ gamma,
                                                 const float* __restrict__ beta,
                                                 float* __restrict__ out) {
    __shared__ float rs[8], rq[8], fin[2];
    const int row = blockIdx.x;
    const int tid = threadIdx.x;
    const int c   = tid << 2;

    float4 x4 = *(const float4*)(out + (size_t)row * NDM + c);
    const float x0 = x4.x, x1 = x4.y, x2 = x4.z, x3 = x4.w;
    float s  = x0 + x1 + x2 + x3;
    float sq = x0 * x0 + x1 * x1 + x2 * x2 + x3 * x3;
#pragma unroll
    for (int off = 16; off; off >>= 1) {
        s  += __shfl_xor_sync(0xffffffffu, s, off);
        sq += __shfl_xor_sync(0xffffffffu, sq, off);
    }
    const int wid = tid >> 5, lane = tid & 31;
    if (lane == 0) { rs[wid] = s; rq[wid] = sq; }
    __syncthreads();
    if (tid == 0) {
        float a = 0.f, b2 = 0.f;
#pragma unroll
        for (int i = 0; i < 8; i++) { a += rs[i]; b2 += rq[i]; }
        fin[0] = a;
        fin[1] = b2;
    }
    __syncthreads();
    const float mu   = fin[0] * (1.0f / NDM);
    const float var  = fin[1] * (1.0f / NDM) - mu * mu;
    const float rstd = rsqrtf(var + 1e-5f);

    float4 g4 = *(const float4*)(gamma + c);
    float4 b4 = *(const float4*)(beta + c);
    float4 r;
    r.x = (x0 - mu) * rstd * g4.x + b4.x;
    r.y = (x1 - mu) * rstd * g4.y + b4.y;
    r.z = (x2 - mu) * rstd * g4.z + b4.z;
    r.w = (x3 - mu) * rstd * g4.w + b4.w;
    *(float4*)(out + (size_t)row * NDM + c) = r;
}

// ---------------------------------------------------------------------------
// Launch
// ---------------------------------------------------------------------------
extern "C" void kernel_launch(void* const* d_in, const int* in_sizes, int n_in,
                              void* d_out, int out_size) {
    const float* Q     = (const float*)d_in[0];
    const float* K     = (const float*)d_in[1];
    const float* V     = (const float*)d_in[2];
    const float* W_Q   = (const float*)d_in[3];
    const float* W_K   = (const float*)d_in[4];
    const float* W_V   = (const float*)d_in[5];
    const float* W_O   = (const float*)d_in[6];
    const float* gamma = (const float*)d_in[7];
    const float* beta  = (const float*)d_in[8];
    float* out = (float*)d_out;

    __half *qh, *kh, *vh, *ctxh, *wtq, *wtk, *wtv, *wto;
    cudaGetSymbolAddress((void**)&qh,   g_Qh);
    cudaGetSymbolAddress((void**)&kh,   g_Kh);
    cudaGetSymbolAddress((void**)&vh,   g_Vh);
    cudaGetSymbolAddress((void**)&ctxh, g_ctxh);
    cudaGetSymbolAddress((void**)&wtq,  g_WTq);
    cudaGetSymbolAddress((void**)&wtk,  g_WTk);
    cudaGetSymbolAddress((void**)&wtv,  g_WTv);
    cudaGetSymbolAddress((void**)&wto,  g_WTo);

    cudaFuncSetAttribute(attn_h, cudaFuncAttributeMaxDynamicSharedMemorySize,
                         ATTN_SMEM_BYTES);
    cudaFuncSetAttribute(gemm_qkv, cudaFuncAttributeMaxDynamicSharedMemorySize,
                         QKV_SMEM);
    cudaFuncSetAttribute(gemm_out, cudaFuncAttributeMaxDynamicSharedMemorySize,
                         OUT_SMEM);

    // weight transposes (fp32 -> fp16 W^T)
    wtrans4_kernel<<<dim3(32, 32, 4), 256>>>(W_Q, W_K, W_V, W_O, wtq, wtk, wtv, wto);

    // QKV projections straight from fp32 inputs (Q pre-scaled by 0.125*log2e)
    gemm_qkv<<<dim3(NDM / 128, NM / 128, 3), 256, QKV_SMEM>>>(
        Q, K, V, wtq, wtk, wtv, qh, kh, vh);

    // attention (fp16, register P, MMA row-sums, 4-warp CTA), writes fp16 ctx
    attn_h<<<dim3(NS / 128, NB * NH), 128, ATTN_SMEM_BYTES>>>(qh, kh, vh, ctxh);

    // output projection + fused residual, then LN
    gemm_out<<<dim3(NDM / 128, NM / 128), 128, OUT_SMEM>>>(ctxh, wto, out, Q);
    ln_kernel<<<NM, 256>>>(gamma, beta, out);
}